// round 1
// baseline (speedup 1.0000x reference)
#include <cuda_runtime.h>
#include <cstdint>

#define T_   10
#define N_   50000
#define R_   50000
#define DIN_ 128
#define D_   64
#define H_   4
#define E_   400000

// ---------------- scratch (static __device__, allowed) ----------------
__device__ float g_deg[N_];
__device__ float g_hw [(size_t)N_ * D_];
__device__ float g_h1 [(size_t)N_ * D_];
__device__ float g_h2 [(size_t)N_ * D_];
__device__ float g_k  [(size_t)R_ * T_ * D_];
__device__ float g_v  [(size_t)R_ * T_ * D_];
__device__ float g_te9[(size_t)R_ * D_];

// ---------------- degree / normalization ----------------
__global__ void deg_init_k(float* deg) {
    int i = blockIdx.x * blockDim.x + threadIdx.x;
    if (i < N_) deg[i] = 1.0f;  // self-loop weight
}
__global__ void deg_acc_k(float* deg, const int* __restrict__ dst, const float* __restrict__ ew) {
    int e = blockIdx.x * blockDim.x + threadIdx.x;
    if (e < E_) atomicAdd(&deg[dst[e]], ew[e]);
}
__global__ void dinv_k(float* deg) {
    int i = blockIdx.x * blockDim.x + threadIdx.x;
    if (i < N_) deg[i] = rsqrtf(deg[i]);  // deg >= 1 always (self loop)
}

// ---------------- GEMM: C[M x 64] = A[M x K] @ W[64 x K]^T ----------------
template <int K>
__global__ void gemm_nt_k(const float* __restrict__ A, const float* __restrict__ W,
                          float* __restrict__ C, int M) {
    __shared__ float Wt[K * 64];      // Wt[k*64+j] = W[j*K+k]
    __shared__ float Ash[128][17];
    int tid = threadIdx.x;            // 128 threads, 1 row each
    for (int i = tid; i < K * 64; i += 128) {
        int k = i >> 6, j = i & 63;
        Wt[i] = W[j * K + k];
    }
    int row0 = blockIdx.x * 128;
    float acc[64];
#pragma unroll
    for (int j = 0; j < 64; j++) acc[j] = 0.f;

    for (int k0 = 0; k0 < K; k0 += 16) {
        __syncthreads();
#pragma unroll
        for (int it = 0; it < 16; it++) {
            int i = it * 128 + tid;
            int r = i >> 4, k = i & 15;
            int gr = row0 + r;
            Ash[r][k] = (gr < M) ? A[(size_t)gr * K + k0 + k] : 0.f;
        }
        __syncthreads();
#pragma unroll
        for (int kk = 0; kk < 16; kk++) {
            float a = Ash[tid][kk];
            const float4* wr = (const float4*)&Wt[(k0 + kk) * 64];
#pragma unroll
            for (int j4 = 0; j4 < 16; j4++) {
                float4 w = wr[j4];
                acc[4 * j4 + 0] = fmaf(a, w.x, acc[4 * j4 + 0]);
                acc[4 * j4 + 1] = fmaf(a, w.y, acc[4 * j4 + 1]);
                acc[4 * j4 + 2] = fmaf(a, w.z, acc[4 * j4 + 2]);
                acc[4 * j4 + 3] = fmaf(a, w.w, acc[4 * j4 + 3]);
            }
        }
    }
    int row = row0 + tid;
    if (row < M) {
        float4* co = (float4*)(C + (size_t)row * 64);
#pragma unroll
        for (int j4 = 0; j4 < 16; j4++)
            co[j4] = make_float4(acc[4 * j4], acc[4 * j4 + 1], acc[4 * j4 + 2], acc[4 * j4 + 3]);
    }
}

// ---------------- aggregation ----------------
// init with self-loop term: out[n] = hw[n] * dinv[n]^2   (norm for self loop = dinv*1*dinv)
__global__ void agg_init_k(const float* __restrict__ hw, const float* __restrict__ dinv,
                           float* __restrict__ out) {
    int idx = blockIdx.x * blockDim.x + threadIdx.x;
    if (idx < N_ * D_) {
        int n = idx >> 6;
        float di = dinv[n];
        out[idx] = hw[idx] * di * di;
    }
}

// random edges: out[dst] += dinv[src]*ew*dinv[dst] * hw[src]  — 8 threads/edge, float4 reductions
__global__ void agg_edges_k(const int* __restrict__ src, const int* __restrict__ dst,
                            const float* __restrict__ ew, const float* __restrict__ dinv,
                            const float* __restrict__ hw, float* __restrict__ out) {
    int tIdx = blockIdx.x * blockDim.x + threadIdx.x;
    int e = tIdx >> 3, sub = tIdx & 7;
    if (e >= E_) return;
    int s = __ldg(src + e), d = __ldg(dst + e);
    float c = __ldg(dinv + s) * __ldg(ew + e) * __ldg(dinv + d);
    const float4* hp = (const float4*)(hw + (size_t)s * 64) + 2 * sub;
    float4 a = __ldg(hp), b = __ldg(hp + 1);
    float* op = out + (size_t)d * 64 + 8 * sub;
    asm volatile("red.global.add.v4.f32 [%0], {%1,%2,%3,%4};"
                 :: "l"(op), "f"(c * a.x), "f"(c * a.y), "f"(c * a.z), "f"(c * a.w) : "memory");
    asm volatile("red.global.add.v4.f32 [%0], {%1,%2,%3,%4};"
                 :: "l"(op + 4), "f"(c * b.x), "f"(c * b.y), "f"(c * b.z), "f"(c * b.w) : "memory");
}

__global__ void bias_relu_k(float* h, const float* __restrict__ b) {
    int idx = blockIdx.x * blockDim.x + threadIdx.x;
    if (idx < N_ * D_) {
        float v = h[idx] + b[idx & 63];
        h[idx] = v > 0.f ? v : 0.f;
    }
}

// ---------------- k/v projection + permutation scatter ----------------
// blockIdx.y: 0 -> K (in_proj rows 64..127), 1 -> V (rows 128..191)
__global__ void kv_proj_k(const float* __restrict__ A, const float* __restrict__ inW,
                          const float* __restrict__ inB, const int* __restrict__ gidx,
                          float* __restrict__ gK, float* __restrict__ gV,
                          float* __restrict__ te9, int t) {
    __shared__ float Wt[64 * 64];
    __shared__ float Ash[128][17];
    __shared__ float bsh[64];
    int yid = blockIdx.y;
    int tid = threadIdx.x;
    const int woff = 64 + yid * 64;
    for (int i = tid; i < 4096; i += 128) {
        int k = i >> 6, j = i & 63;
        Wt[i] = inW[(woff + j) * 64 + k];
    }
    if (tid < 64) bsh[tid] = inB[woff + tid];

    int row0 = blockIdx.x * 128;
    float acc[64];
#pragma unroll
    for (int j = 0; j < 64; j++) acc[j] = 0.f;

    for (int k0 = 0; k0 < 64; k0 += 16) {
        __syncthreads();
#pragma unroll
        for (int it = 0; it < 16; it++) {
            int i = it * 128 + tid;
            int r = i >> 4, k = i & 15;
            int gr = row0 + r;
            Ash[r][k] = (gr < N_) ? A[(size_t)gr * 64 + k0 + k] : 0.f;
        }
        __syncthreads();
#pragma unroll
        for (int kk = 0; kk < 16; kk++) {
            float a = Ash[tid][kk];
            const float4* wr = (const float4*)&Wt[(k0 + kk) * 64];
#pragma unroll
            for (int j4 = 0; j4 < 16; j4++) {
                float4 w = wr[j4];
                acc[4 * j4 + 0] = fmaf(a, w.x, acc[4 * j4 + 0]);
                acc[4 * j4 + 1] = fmaf(a, w.y, acc[4 * j4 + 1]);
                acc[4 * j4 + 2] = fmaf(a, w.z, acc[4 * j4 + 2]);
                acc[4 * j4 + 3] = fmaf(a, w.w, acc[4 * j4 + 3]);
            }
        }
    }
    int row = row0 + tid;
    if (row < N_) {
        int r = __ldg(gidx + row);
        float* op = (yid ? gV : gK) + ((size_t)r * T_ + t) * 64;
        float4* op4 = (float4*)op;
#pragma unroll
        for (int j4 = 0; j4 < 16; j4++)
            op4[j4] = make_float4(acc[4 * j4 + 0] + bsh[4 * j4 + 0],
                                  acc[4 * j4 + 1] + bsh[4 * j4 + 1],
                                  acc[4 * j4 + 2] + bsh[4 * j4 + 2],
                                  acc[4 * j4 + 3] + bsh[4 * j4 + 3]);
        if (yid == 0 && t == T_ - 1) {
            float4* tp = (float4*)(te9 + (size_t)r * 64);
            const float4* ap = (const float4*)(A + (size_t)row * 64);
#pragma unroll
            for (int j4 = 0; j4 < 16; j4++) tp[j4] = ap[j4];
        }
    }
}

// ---------------- tail: q-proj + attention(last query) + out_proj + LN1 + fc + LN2 ----------------
#define TAIL_WARPS 4
#define TAIL_SMEM  ((12288 + 704 + TAIL_WARPS * 1456) * 4)

__device__ __forceinline__ float warp_sum(float v) {
#pragma unroll
    for (int off = 16; off; off >>= 1) v += __shfl_xor_sync(0xffffffffu, v, off);
    return v;
}

__global__ void tail_k(const float* __restrict__ inW, const float* __restrict__ inB,
                       const float* __restrict__ outW, const float* __restrict__ outB,
                       const float* __restrict__ w1, const float* __restrict__ w2,
                       const float* __restrict__ w3, const float* __restrict__ w4,
                       const float* __restrict__ ln1g, const float* __restrict__ ln1b,
                       const float* __restrict__ ln2g, const float* __restrict__ ln2b,
                       const float* __restrict__ fcW, const float* __restrict__ fcB,
                       const float* __restrict__ te9, const float* __restrict__ gK,
                       const float* __restrict__ gV, float* __restrict__ out) {
    extern __shared__ float sh[];
    float* Wq = sh;             // 4096 : Wq[k*64+j] = in_proj_w[j*64+k]  (q rows 0..63)
    float* Wo = sh + 4096;      // 4096
    float* Wf = sh + 8192;      // 4096
    float* cv = sh + 12288;     // 704 consts

    int tid = threadIdx.x;
    for (int i = tid; i < 4096; i += 128) {
        int k = i >> 6, j = i & 63;
        Wq[i] = inW[j * 64 + k];
        Wo[i] = outW[j * 64 + k];
        Wf[i] = fcW[j * 64 + k];
    }
    if (tid < 64) {
        cv[tid]       = inB[tid];            // bq
        cv[64 + tid]  = outB[tid];           // bo
        cv[128 + tid] = fcB[tid];            // bfc
        cv[192 + tid] = w1[(T_ - 1) * 64 + tid];
        cv[256 + tid] = w2[(T_ - 1) * 64 + tid];
        cv[320 + tid] = ln1g[tid];
        cv[384 + tid] = ln1b[tid];
        cv[448 + tid] = w3[tid];
        cv[512 + tid] = w4[tid];
        cv[576 + tid] = ln2g[tid];
        cv[640 + tid] = ln2b[tid];
    }
    __syncthreads();

    int warp = tid >> 5, lane = tid & 31;
    float* wb   = cv + 704 + warp * 1456;
    float* pvec = wb;          // 64
    float* pq   = wb + 64;     // 64 (q, later attn-out vec)
    float* kb   = wb + 128;    // 640
    float* vb   = wb + 768;    // 640
    float* sc   = wb + 1408;   // 40 (+pad)

    int gw = blockIdx.x * TAIL_WARPS + warp;
    int nw = gridDim.x * TAIL_WARPS;

    for (int r = gw; r < R_; r += nw) {
        // load te9 row + k/v (coalesced)
        pvec[lane]      = te9[(size_t)r * 64 + lane];
        pvec[lane + 32] = te9[(size_t)r * 64 + lane + 32];
        for (int i = lane; i < 640; i += 32) {
            kb[i] = gK[(size_t)r * 640 + i];
            vb[i] = gV[(size_t)r * 640 + i];
        }
        __syncwarp();

        // q = te9 @ Wq^T + bq
        float q0 = cv[lane], q1 = cv[lane + 32];
        for (int k = 0; k < 64; k++) {
            float xv = pvec[k];
            q0 = fmaf(xv, Wq[k * 64 + lane], q0);
            q1 = fmaf(xv, Wq[k * 64 + lane + 32], q1);
        }
        pq[lane] = q0; pq[lane + 32] = q1;
        __syncwarp();

        // scores[h][t] = (q_h . k_{t,h}) / 4     (mask is all-false: global_idx is a permutation)
        for (int p = lane; p < H_ * T_; p += 32) {
            int h = p / T_, tt = p - h * T_;
            const float* qh = pq + h * 16;
            const float* kh = kb + tt * 64 + h * 16;
            float s = 0.f;
#pragma unroll
            for (int d = 0; d < 16; d++) s = fmaf(qh[d], kh[d], s);
            sc[p] = s * 0.25f;
        }
        __syncwarp();

        // softmax over t, per head (lanes 0..3)
        if (lane < H_) {
            float mx = -1e30f;
#pragma unroll
            for (int tt = 0; tt < T_; tt++) mx = fmaxf(mx, sc[lane * T_ + tt]);
            float sm = 0.f;
#pragma unroll
            for (int tt = 0; tt < T_; tt++) {
                float ev = __expf(sc[lane * T_ + tt] - mx);
                sc[lane * T_ + tt] = ev; sm += ev;
            }
            float inv = 1.f / sm;
#pragma unroll
            for (int tt = 0; tt < T_; tt++) sc[lane * T_ + tt] *= inv;
        }
        __syncwarp();

        // ao[j] = sum_t attn[h(j)][t] * v[t][j]
        int h0 = lane >> 4, h1 = (lane + 32) >> 4;
        float a0 = 0.f, a1 = 0.f;
#pragma unroll
        for (int tt = 0; tt < T_; tt++) {
            a0 = fmaf(sc[h0 * T_ + tt], vb[tt * 64 + lane], a0);
            a1 = fmaf(sc[h1 * T_ + tt], vb[tt * 64 + lane + 32], a1);
        }
        pq[lane] = a0; pq[lane + 32] = a1;
        __syncwarp();

        // attn_out = ao @ Wo^T + bo
        float o0 = cv[64 + lane], o1 = cv[64 + lane + 32];
        for (int k = 0; k < 64; k++) {
            float xv = pq[k];
            o0 = fmaf(xv, Wo[k * 64 + lane], o0);
            o1 = fmaf(xv, Wo[k * 64 + lane + 32], o1);
        }

        // y = w1*te9 + w2*attn_out ; LN1
        float y0 = cv[192 + lane] * pvec[lane] + cv[256 + lane] * o0;
        float y1 = cv[192 + lane + 32] * pvec[lane + 32] + cv[256 + lane + 32] * o1;
        float mu = warp_sum(y0 + y1) * (1.f / 64.f);
        float d0 = y0 - mu, d1 = y1 - mu;
        float var = warp_sum(d0 * d0 + d1 * d1) * (1.f / 64.f);
        float rs = rsqrtf(var + 1e-5f);
        float f0 = d0 * rs * cv[320 + lane] + cv[384 + lane];
        float f1 = d1 * rs * cv[320 + lane + 32] + cv[384 + lane + 32];
        __syncwarp();
        pvec[lane] = f0; pvec[lane + 32] = f1;
        __syncwarp();

        // u = final @ fc^T + fcb
        float u0 = cv[128 + lane], u1 = cv[128 + lane + 32];
        for (int k = 0; k < 64; k++) {
            float xv = pvec[k];
            u0 = fmaf(xv, Wf[k * 64 + lane], u0);
            u1 = fmaf(xv, Wf[k * 64 + lane + 32], u1);
        }
        // z = w3*final + w4*u ; LN2 -> out
        float z0 = cv[448 + lane] * f0 + cv[512 + lane] * u0;
        float z1 = cv[448 + lane + 32] * f1 + cv[512 + lane + 32] * u1;
        float mu2 = warp_sum(z0 + z1) * (1.f / 64.f);
        float e0 = z0 - mu2, e1 = z1 - mu2;
        float var2 = warp_sum(e0 * e0 + e1 * e1) * (1.f / 64.f);
        float rs2 = rsqrtf(var2 + 1e-5f);
        out[(size_t)r * 64 + lane]      = e0 * rs2 * cv[576 + lane] + cv[640 + lane];
        out[(size_t)r * 64 + lane + 32] = e1 * rs2 * cv[576 + lane + 32] + cv[640 + lane + 32];
        __syncwarp();
    }
}

// ---------------- launch ----------------
extern "C" void kernel_launch(void* const* d_in, const int* in_sizes, int n_in,
                              void* d_out, int out_size) {
    const float* x          = (const float*)d_in[0];
    const int*   edge_index = (const int*)  d_in[1];
    const float* edge_weight= (const float*)d_in[2];
    const int*   global_idx = (const int*)  d_in[3];
    const float* gcn1_w     = (const float*)d_in[4];
    const float* gcn1_b     = (const float*)d_in[5];
    const float* gcn2_w     = (const float*)d_in[6];
    const float* gcn2_b     = (const float*)d_in[7];
    const float* in_proj_w  = (const float*)d_in[8];
    const float* in_proj_b  = (const float*)d_in[9];
    const float* out_proj_w = (const float*)d_in[10];
    const float* out_proj_b = (const float*)d_in[11];
    const float* w1         = (const float*)d_in[12];
    const float* w2         = (const float*)d_in[13];
    const float* w3         = (const float*)d_in[14];
    const float* w4         = (const float*)d_in[15];
    const float* ln1_g      = (const float*)d_in[16];
    const float* ln1_b      = (const float*)d_in[17];
    const float* ln2_g      = (const float*)d_in[18];
    const float* ln2_b      = (const float*)d_in[19];
    const float* fc_w       = (const float*)d_in[20];
    const float* fc_b       = (const float*)d_in[21];
    float* out = (float*)d_out;

    float *deg, *hw, *h1, *h2, *gk, *gv, *te9;
    cudaGetSymbolAddress((void**)&deg, g_deg);
    cudaGetSymbolAddress((void**)&hw,  g_hw);
    cudaGetSymbolAddress((void**)&h1,  g_h1);
    cudaGetSymbolAddress((void**)&h2,  g_h2);
    cudaGetSymbolAddress((void**)&gk,  g_k);
    cudaGetSymbolAddress((void**)&gv,  g_v);
    cudaGetSymbolAddress((void**)&te9, g_te9);

    cudaFuncSetAttribute(tail_k, cudaFuncAttributeMaxDynamicSharedMemorySize, TAIL_SMEM);

    const int NB_N  = (N_ + 255) / 256;          // 196
    const int NB_E  = (E_ + 255) / 256;          // 1563
    const int NB_NV = (N_ * D_ + 255) / 256;     // 12500
    const int NB_EA = (E_ * 8 + 255) / 256;      // 12500
    const int NB_G  = (N_ + 127) / 128;          // 391

    for (int t = 0; t < T_; t++) {
        const float* xt   = x + (size_t)t * N_ * DIN_;
        const int*   srct = edge_index + (size_t)t * 2 * E_;
        const int*   dstt = srct + E_;
        const float* ewt  = edge_weight + (size_t)t * E_;
        const int*   gidx = global_idx + (size_t)t * R_;

        deg_init_k<<<NB_N, 256>>>(deg);
        deg_acc_k <<<NB_E, 256>>>(deg, dstt, ewt);
        dinv_k    <<<NB_N, 256>>>(deg);

        // layer 1
        gemm_nt_k<128><<<NB_G, 128>>>(xt, gcn1_w, hw, N_);
        agg_init_k <<<NB_NV, 256>>>(hw, deg, h1);
        agg_edges_k<<<NB_EA, 256>>>(srct, dstt, ewt, deg, hw, h1);
        bias_relu_k<<<NB_NV, 256>>>(h1, gcn1_b);

        // layer 2
        gemm_nt_k<64><<<NB_G, 128>>>(h1, gcn2_w, hw, N_);
        agg_init_k <<<NB_NV, 256>>>(hw, deg, h2);
        agg_edges_k<<<NB_EA, 256>>>(srct, dstt, ewt, deg, hw, h2);
        bias_relu_k<<<NB_NV, 256>>>(h2, gcn2_b);

        // k/v projection + permutation scatter (+ te9 at t=9)
        kv_proj_k<<<dim3(NB_G, 2), 128>>>(h2, in_proj_w, in_proj_b, gidx, gk, gv, te9, t);
    }

    tail_k<<<296, 128, TAIL_SMEM>>>(in_proj_w, in_proj_b, out_proj_w, out_proj_b,
                                    w1, w2, w3, w4, ln1_g, ln1_b, ln2_g, ln2_b,
                                    fc_w, fc_b, te9, gk, gv, out);
}

// round 3
// speedup vs baseline: 1.5524x; 1.5524x over previous
#include <cuda_runtime.h>
#include <cstdint>

#define T_   10
#define N_   50000
#define R_   50000
#define DIN_ 128
#define D_   64
#define H_   4
#define E_   400000
#define MTOT (T_ * N_)   // 500000

// ---------------- scratch ----------------
__device__ float g_deg[(size_t)MTOT];
__device__ float g_hw [(size_t)MTOT * D_];
__device__ float g_h1 [(size_t)MTOT * D_];
__device__ float g_h2 [(size_t)MTOT * D_];
__device__ float g_k  [(size_t)R_ * T_ * D_];
__device__ float g_v  [(size_t)R_ * T_ * D_];
__device__ float g_te9[(size_t)R_ * D_];

// ---------------- f32x2 helpers ----------------
__device__ __forceinline__ unsigned long long fma2(unsigned long long a,
                                                   unsigned long long b,
                                                   unsigned long long c) {
    unsigned long long d;
    asm("fma.rn.f32x2 %0, %1, %2, %3;" : "=l"(d) : "l"(a), "l"(b), "l"(c));
    return d;
}
__device__ __forceinline__ unsigned long long dup2(float x) {
    unsigned long long d;
    asm("mov.b64 %0, {%1, %1};" : "=l"(d) : "f"(x));
    return d;
}
__device__ __forceinline__ float2 unpack2(unsigned long long v) {
    float2 r;
    asm("mov.b64 {%0, %1}, %2;" : "=f"(r.x), "=f"(r.y) : "l"(v));
    return r;
}

// ---------------- degree / normalization (batched over T) ----------------
__global__ void deg_init_all(float* deg) {
    int i = blockIdx.x * blockDim.x + threadIdx.x;
    if (i < MTOT) deg[i] = 1.0f;  // self loop
}
__global__ void deg_acc_all(float* deg, const int* __restrict__ edge_index,
                            const float* __restrict__ ew) {
    int t = blockIdx.y;
    int e = blockIdx.x * blockDim.x + threadIdx.x;
    if (e < E_) {
        const int* dst = edge_index + (size_t)t * 2 * E_ + E_;
        atomicAdd(&deg[t * N_ + dst[e]], ew[(size_t)t * E_ + e]);
    }
}
__global__ void dinv_all(float* deg) {
    int i = blockIdx.x * blockDim.x + threadIdx.x;
    if (i < MTOT) deg[i] = rsqrtf(deg[i]);
}

// ---------------- fused batched GEMM ----------------
// C[M x BN] = act(A) @ Wt, act = (abias? relu(x+b) : x)
// EPI 0: hw = C ; hout = C * dinv[row]^2
// EPI 1: C += ebias ; scatter to gK/gV via gidx ; (K|V split at col 64)
template <int K, int BN, int EPI>
__global__ void __launch_bounds__(256, 2)
gemm_all_k(const float* __restrict__ A, const float* __restrict__ Wsrc,
           const float* __restrict__ abias,
           const float* __restrict__ dinv, float* __restrict__ hw, float* __restrict__ hout,
           const float* __restrict__ ebias, const int* __restrict__ gidx,
           float* __restrict__ gK, float* __restrict__ gV) {
    constexpr int BM  = 16384 / BN;   // 256 (BN=64) or 128 (BN=128)
    constexpr int CG  = BN / 8;       // colgroups
    constexpr int NT  = K / 16;       // k-tiles
    constexpr int LD4 = (BM * 16) / (256 * 4);  // float4 loads per thread per tile

    extern __shared__ float smem[];
    float* Wsh = smem;            // K*BN  : Wsh[k*BN+j] = Wsrc[j*K+k]
    float* Ash = smem + K * BN;   // 2 * 16 * BM (transposed: [k][row])

    const int tid = threadIdx.x;
    for (int i = tid; i < K * BN; i += 256) {
        int k = i >> (BN == 64 ? 6 : 7);
        int j = i & (BN - 1);
        Wsh[i] = Wsrc[j * K + k];
    }

    const int cg = tid & (CG - 1);
    const int rg = tid >> (CG == 8 ? 3 : 4);
    const long long row0 = (long long)blockIdx.x * BM;

    float4 areg[LD4];
    auto lda = [&](int kt) {
#pragma unroll
        for (int it = 0; it < LD4; it++) {
            int idx = it * 256 + tid;
            int r = idx >> 2, kq = idx & 3;
            long long grow = row0 + r;
            float4 v = make_float4(0.f, 0.f, 0.f, 0.f);
            if (grow < MTOT) {
                v = *(const float4*)(A + grow * K + kt * 16 + kq * 4);
                if (abias) {
                    float4 b = *(const float4*)(abias + kt * 16 + kq * 4);
                    v.x = fmaxf(v.x + b.x, 0.f);
                    v.y = fmaxf(v.y + b.y, 0.f);
                    v.z = fmaxf(v.z + b.z, 0.f);
                    v.w = fmaxf(v.w + b.w, 0.f);
                }
            }
            areg[it] = v;
        }
    };
    auto sts = [&](int buf) {
        float* dst = Ash + buf * 16 * BM;
#pragma unroll
        for (int it = 0; it < LD4; it++) {
            int idx = it * 256 + tid;
            int r = idx >> 2, kq = idx & 3;
            float* p = dst + (kq * 4) * BM + r;
            p[0 * BM] = areg[it].x;
            p[1 * BM] = areg[it].y;
            p[2 * BM] = areg[it].z;
            p[3 * BM] = areg[it].w;
        }
    };

    unsigned long long acc[4][8];
#pragma unroll
    for (int p = 0; p < 4; p++)
#pragma unroll
        for (int c = 0; c < 8; c++) acc[p][c] = 0ull;

    lda(0);
    for (int kt = 0; kt < NT; kt++) {
        sts(kt & 1);
        __syncthreads();
        if (kt + 1 < NT) lda(kt + 1);
        const float* As = Ash + (kt & 1) * 16 * BM;
        const float* Wk = Wsh + kt * 16 * BN;   // FIX: k-tile offset into weight tile
#pragma unroll
        for (int kk = 0; kk < 16; kk++) {
            const ulonglong2* ap = (const ulonglong2*)(As + kk * BM + rg * 8);
            ulonglong2 a01 = ap[0], a23 = ap[1];
            unsigned long long av0 = a01.x, av1 = a01.y, av2 = a23.x, av3 = a23.y;
            const float4* wp = (const float4*)(Wk + kk * BN + cg * 8);
            float4 w0 = wp[0], w1 = wp[1];
            unsigned long long wd[8] = {dup2(w0.x), dup2(w0.y), dup2(w0.z), dup2(w0.w),
                                        dup2(w1.x), dup2(w1.y), dup2(w1.z), dup2(w1.w)};
#pragma unroll
            for (int c = 0; c < 8; c++) {
                acc[0][c] = fma2(av0, wd[c], acc[0][c]);
                acc[1][c] = fma2(av1, wd[c], acc[1][c]);
                acc[2][c] = fma2(av2, wd[c], acc[2][c]);
                acc[3][c] = fma2(av3, wd[c], acc[3][c]);
            }
        }
        __syncthreads();
    }

    // epilogue
#pragma unroll
    for (int p = 0; p < 4; p++) {
        float2 f[8];
#pragma unroll
        for (int c = 0; c < 8; c++) f[c] = unpack2(acc[p][c]);
        long long r0 = row0 + rg * 8 + 2 * p;
#pragma unroll
        for (int half = 0; half < 2; half++) {
            long long r = r0 + half;
            if (r >= MTOT) continue;
            float v[8];
#pragma unroll
            for (int c = 0; c < 8; c++) v[c] = half ? f[c].y : f[c].x;
            if (EPI == 0) {
                float di = dinv[r];
                float di2 = di * di;
                float4* hwp = (float4*)(hw + r * 64 + cg * 8);
                float4* hop = (float4*)(hout + r * 64 + cg * 8);
                hwp[0] = make_float4(v[0], v[1], v[2], v[3]);
                hwp[1] = make_float4(v[4], v[5], v[6], v[7]);
                hop[0] = make_float4(v[0] * di2, v[1] * di2, v[2] * di2, v[3] * di2);
                hop[1] = make_float4(v[4] * di2, v[5] * di2, v[6] * di2, v[7] * di2);
            } else {
                int j0 = cg * 8;
                const float4* bp = (const float4*)(ebias + j0);
                float4 b0 = __ldg(bp), b1 = __ldg(bp + 1);
                unsigned rr = (unsigned)r;
                unsigned t = rr / (unsigned)N_;
                unsigned n = rr - t * (unsigned)N_;
                int ridx = __ldg(gidx + (size_t)t * R_ + n);
                float* base = (j0 < 64 ? gK : gV) + ((size_t)ridx * T_ + t) * 64 + (j0 & 63);
                float4* op = (float4*)base;
                op[0] = make_float4(v[0] + b0.x, v[1] + b0.y, v[2] + b0.z, v[3] + b0.w);
                op[1] = make_float4(v[4] + b1.x, v[5] + b1.y, v[6] + b1.z, v[7] + b1.w);
            }
        }
    }
}

// ---------------- edge aggregation (batched over T) ----------------
__global__ void agg_all_k(const int* __restrict__ edge_index, const float* __restrict__ ew_all,
                          const float* __restrict__ dinv, const float* __restrict__ hw,
                          float* __restrict__ out) {
    int t = blockIdx.y;
    int tIdx = blockIdx.x * blockDim.x + threadIdx.x;
    int e = tIdx >> 3, sub = tIdx & 7;
    if (e >= E_) return;
    const int* src = edge_index + (size_t)t * 2 * E_;
    const int* dst = src + E_;
    int s = __ldg(src + e), d = __ldg(dst + e);
    float w = __ldg(ew_all + (size_t)t * E_ + e);
    float c = __ldg(dinv + t * N_ + s) * w * __ldg(dinv + t * N_ + d);
    const float4* hp = (const float4*)(hw + ((size_t)t * N_ + s) * 64) + 2 * sub;
    float4 a = __ldg(hp), b = __ldg(hp + 1);
    float* op = out + ((size_t)t * N_ + d) * 64 + 8 * sub;
    asm volatile("red.global.add.v4.f32 [%0], {%1,%2,%3,%4};"
                 :: "l"(op), "f"(c * a.x), "f"(c * a.y), "f"(c * a.z), "f"(c * a.w) : "memory");
    asm volatile("red.global.add.v4.f32 [%0], {%1,%2,%3,%4};"
                 :: "l"(op + 4), "f"(c * b.x), "f"(c * b.y), "f"(c * b.z), "f"(c * b.w) : "memory");
}

// ---------------- te9: relu(h2[t=9] + b2) scattered by gidx ----------------
__global__ void te9_k(const float* __restrict__ h2, const float* __restrict__ b2,
                      const int* __restrict__ gidx, float* __restrict__ te9) {
    int idx = blockIdx.x * blockDim.x + threadIdx.x;
    if (idx >= N_ * D_) return;
    int n = idx >> 6, c = idx & 63;
    float v = fmaxf(h2[((size_t)9 * N_ + n) * 64 + c] + b2[c], 0.f);
    te9[(size_t)__ldg(gidx + (size_t)9 * R_ + n) * 64 + c] = v;
}

// ---------------- tail ----------------
#define TAIL_WARPS 4
#define TAIL_SMEM  ((12288 + 704 + TAIL_WARPS * 1456) * 4)

__device__ __forceinline__ float warp_sum(float v) {
#pragma unroll
    for (int off = 16; off; off >>= 1) v += __shfl_xor_sync(0xffffffffu, v, off);
    return v;
}

__global__ void tail_k(const float* __restrict__ inW, const float* __restrict__ inB,
                       const float* __restrict__ outW, const float* __restrict__ outB,
                       const float* __restrict__ w1, const float* __restrict__ w2,
                       const float* __restrict__ w3, const float* __restrict__ w4,
                       const float* __restrict__ ln1g, const float* __restrict__ ln1b,
                       const float* __restrict__ ln2g, const float* __restrict__ ln2b,
                       const float* __restrict__ fcW, const float* __restrict__ fcB,
                       const float* __restrict__ te9, const float* __restrict__ gK,
                       const float* __restrict__ gV, float* __restrict__ out) {
    extern __shared__ float sh[];
    float* Wq = sh;
    float* Wo = sh + 4096;
    float* Wf = sh + 8192;
    float* cv = sh + 12288;

    int tid = threadIdx.x;
    for (int i = tid; i < 4096; i += 128) {
        int k = i >> 6, j = i & 63;
        Wq[i] = inW[j * 64 + k];
        Wo[i] = outW[j * 64 + k];
        Wf[i] = fcW[j * 64 + k];
    }
    if (tid < 64) {
        cv[tid]       = inB[tid];
        cv[64 + tid]  = outB[tid];
        cv[128 + tid] = fcB[tid];
        cv[192 + tid] = w1[(T_ - 1) * 64 + tid];
        cv[256 + tid] = w2[(T_ - 1) * 64 + tid];
        cv[320 + tid] = ln1g[tid];
        cv[384 + tid] = ln1b[tid];
        cv[448 + tid] = w3[tid];
        cv[512 + tid] = w4[tid];
        cv[576 + tid] = ln2g[tid];
        cv[640 + tid] = ln2b[tid];
    }
    __syncthreads();

    int warp = tid >> 5, lane = tid & 31;
    float* wb   = cv + 704 + warp * 1456;
    float* pvec = wb;
    float* pq   = wb + 64;
    float* kb   = wb + 128;
    float* vb   = wb + 768;
    float* sc   = wb + 1408;

    int gw = blockIdx.x * TAIL_WARPS + warp;
    int nw = gridDim.x * TAIL_WARPS;

    for (int r = gw; r < R_; r += nw) {
        pvec[lane]      = te9[(size_t)r * 64 + lane];
        pvec[lane + 32] = te9[(size_t)r * 64 + lane + 32];
        for (int i = lane; i < 640; i += 32) {
            kb[i] = gK[(size_t)r * 640 + i];
            vb[i] = gV[(size_t)r * 640 + i];
        }
        __syncwarp();

        float q0 = cv[lane], q1 = cv[lane + 32];
        for (int k = 0; k < 64; k++) {
            float xv = pvec[k];
            q0 = fmaf(xv, Wq[k * 64 + lane], q0);
            q1 = fmaf(xv, Wq[k * 64 + lane + 32], q1);
        }
        pq[lane] = q0; pq[lane + 32] = q1;
        __syncwarp();

        for (int p = lane; p < H_ * T_; p += 32) {
            int h = p / T_, tt = p - h * T_;
            const float* qh = pq + h * 16;
            const float* kh = kb + tt * 64 + h * 16;
            float s = 0.f;
#pragma unroll
            for (int d = 0; d < 16; d++) s = fmaf(qh[d], kh[d], s);
            sc[p] = s * 0.25f;
        }
        __syncwarp();

        if (lane < H_) {
            float mx = -1e30f;
#pragma unroll
            for (int tt = 0; tt < T_; tt++) mx = fmaxf(mx, sc[lane * T_ + tt]);
            float sm = 0.f;
#pragma unroll
            for (int tt = 0; tt < T_; tt++) {
                float ev = __expf(sc[lane * T_ + tt] - mx);
                sc[lane * T_ + tt] = ev; sm += ev;
            }
            float inv = 1.f / sm;
#pragma unroll
            for (int tt = 0; tt < T_; tt++) sc[lane * T_ + tt] *= inv;
        }
        __syncwarp();

        int h0 = lane >> 4, h1 = (lane + 32) >> 4;
        float a0 = 0.f, a1 = 0.f;
#pragma unroll
        for (int tt = 0; tt < T_; tt++) {
            a0 = fmaf(sc[h0 * T_ + tt], vb[tt * 64 + lane], a0);
            a1 = fmaf(sc[h1 * T_ + tt], vb[tt * 64 + lane + 32], a1);
        }
        pq[lane] = a0; pq[lane + 32] = a1;
        __syncwarp();

        float o0 = cv[64 + lane], o1 = cv[64 + lane + 32];
        for (int k = 0; k < 64; k++) {
            float xv = pq[k];
            o0 = fmaf(xv, Wo[k * 64 + lane], o0);
            o1 = fmaf(xv, Wo[k * 64 + lane + 32], o1);
        }

        float y0 = cv[192 + lane] * pvec[lane] + cv[256 + lane] * o0;
        float y1 = cv[192 + lane + 32] * pvec[lane + 32] + cv[256 + lane + 32] * o1;
        float mu = warp_sum(y0 + y1) * (1.f / 64.f);
        float d0 = y0 - mu, d1 = y1 - mu;
        float var = warp_sum(d0 * d0 + d1 * d1) * (1.f / 64.f);
        float rs = rsqrtf(var + 1e-5f);
        float f0 = d0 * rs * cv[320 + lane] + cv[384 + lane];
        float f1 = d1 * rs * cv[320 + lane + 32] + cv[384 + lane + 32];
        __syncwarp();
        pvec[lane] = f0; pvec[lane + 32] = f1;
        __syncwarp();

        float u0 = cv[128 + lane], u1 = cv[128 + lane + 32];
        for (int k = 0; k < 64; k++) {
            float xv = pvec[k];
            u0 = fmaf(xv, Wf[k * 64 + lane], u0);
            u1 = fmaf(xv, Wf[k * 64 + lane + 32], u1);
        }
        float z0 = cv[448 + lane] * f0 + cv[512 + lane] * u0;
        float z1 = cv[448 + lane + 32] * f1 + cv[512 + lane + 32] * u1;
        float mu2 = warp_sum(z0 + z1) * (1.f / 64.f);
        float e0 = z0 - mu2, e1 = z1 - mu2;
        float var2 = warp_sum(e0 * e0 + e1 * e1) * (1.f / 64.f);
        float rs2 = rsqrtf(var2 + 1e-5f);
        out[(size_t)r * 64 + lane]      = e0 * rs2 * cv[576 + lane] + cv[640 + lane];
        out[(size_t)r * 64 + lane + 32] = e1 * rs2 * cv[576 + lane + 32] + cv[640 + lane + 32];
        __syncwarp();
    }
}

// ---------------- launch ----------------
extern "C" void kernel_launch(void* const* d_in, const int* in_sizes, int n_in,
                              void* d_out, int out_size) {
    const float* x          = (const float*)d_in[0];
    const int*   edge_index = (const int*)  d_in[1];
    const float* edge_weight= (const float*)d_in[2];
    const int*   global_idx = (const int*)  d_in[3];
    const float* gcn1_w     = (const float*)d_in[4];
    const float* gcn1_b     = (const float*)d_in[5];
    const float* gcn2_w     = (const float*)d_in[6];
    const float* gcn2_b     = (const float*)d_in[7];
    const float* in_proj_w  = (const float*)d_in[8];
    const float* in_proj_b  = (const float*)d_in[9];
    const float* out_proj_w = (const float*)d_in[10];
    const float* out_proj_b = (const float*)d_in[11];
    const float* w1         = (const float*)d_in[12];
    const float* w2         = (const float*)d_in[13];
    const float* w3         = (const float*)d_in[14];
    const float* w4         = (const float*)d_in[15];
    const float* ln1_g      = (const float*)d_in[16];
    const float* ln1_b      = (const float*)d_in[17];
    const float* ln2_g      = (const float*)d_in[18];
    const float* ln2_b      = (const float*)d_in[19];
    const float* fc_w       = (const float*)d_in[20];
    const float* fc_b       = (const float*)d_in[21];
    float* out = (float*)d_out;

    float *deg, *hw, *h1, *h2, *gk, *gv, *te9;
    cudaGetSymbolAddress((void**)&deg, g_deg);
    cudaGetSymbolAddress((void**)&hw,  g_hw);
    cudaGetSymbolAddress((void**)&h1,  g_h1);
    cudaGetSymbolAddress((void**)&h2,  g_h2);
    cudaGetSymbolAddress((void**)&gk,  g_k);
    cudaGetSymbolAddress((void**)&gv,  g_v);
    cudaGetSymbolAddress((void**)&te9, g_te9);

    const int SM1 = (128 * 64 + 2 * 16 * 256) * 4;   // 65536
    const int SM2 = (64 * 64 + 2 * 16 * 256) * 4;    // 49152
    const int SM3 = (64 * 128 + 2 * 16 * 128) * 4;   // 49152
    cudaFuncSetAttribute((const void*)gemm_all_k<128, 64, 0>,
                         cudaFuncAttributeMaxDynamicSharedMemorySize, SM1);
    cudaFuncSetAttribute((const void*)gemm_all_k<64, 64, 0>,
                         cudaFuncAttributeMaxDynamicSharedMemorySize, SM2);
    cudaFuncSetAttribute((const void*)gemm_all_k<64, 128, 1>,
                         cudaFuncAttributeMaxDynamicSharedMemorySize, SM3);
    cudaFuncSetAttribute(tail_k, cudaFuncAttributeMaxDynamicSharedMemorySize, TAIL_SMEM);

    const int NB_M   = (MTOT + 255) / 256;    // 1954
    const int NB_G1  = (MTOT + 255) / 256;    // BM=256 -> 1954 blocks
    const int NB_G3  = (MTOT + 127) / 128;    // BM=128 -> 3907 blocks
    const dim3 GB_E((E_ + 255) / 256, T_);
    const dim3 GB_A((E_ * 8 + 255) / 256, T_);

    deg_init_all<<<NB_M, 256>>>(deg);
    deg_acc_all <<<GB_E, 256>>>(deg, edge_index, edge_weight);
    dinv_all    <<<NB_M, 256>>>(deg);

    gemm_all_k<128, 64, 0><<<NB_G1, 256, SM1>>>(x, gcn1_w, nullptr,
                                                deg, hw, h1,
                                                nullptr, nullptr, nullptr, nullptr);
    agg_all_k<<<GB_A, 256>>>(edge_index, edge_weight, deg, hw, h1);

    gemm_all_k<64, 64, 0><<<NB_G1, 256, SM2>>>(h1, gcn2_w, gcn1_b,
                                               deg, hw, h2,
                                               nullptr, nullptr, nullptr, nullptr);
    agg_all_k<<<GB_A, 256>>>(edge_index, edge_weight, deg, hw, h2);

    gemm_all_k<64, 128, 1><<<NB_G3, 256, SM3>>>(h2, in_proj_w + 64 * 64, gcn2_b,
                                                nullptr, nullptr, nullptr,
                                                in_proj_b + 64, global_idx, gk, gv);
    te9_k<<<(N_ * D_ + 255) / 256, 256>>>(h2, gcn2_b, global_idx, te9);

    tail_k<<<296, 128, TAIL_SMEM>>>(in_proj_w, in_proj_b, out_proj_w, out_proj_b,
                                    w1, w2, w3, w4, ln1_g, ln1_b, ln2_g, ln2_b,
                                    fc_w, fc_b, te9, gk, gv, out);
}

// round 4
// speedup vs baseline: 1.9563x; 1.2602x over previous
#include <cuda_runtime.h>
#include <cstdint>

#define T_   10
#define N_   50000
#define R_   50000
#define DIN_ 128
#define D_   64
#define H_   4
#define E_   400000
#define MTOT (T_ * N_)   // 500000

// ---------------- scratch ----------------
__device__ float g_deg[(size_t)MTOT];
__device__ float g_hw [(size_t)MTOT * D_];
__device__ float g_h1 [(size_t)MTOT * D_];
__device__ float g_h2 [(size_t)MTOT * D_];
__device__ float g_k  [(size_t)R_ * T_ * D_];
__device__ float g_v  [(size_t)R_ * T_ * D_];
__device__ float g_te9[(size_t)R_ * D_];

// ---------------- degree / normalization (batched over T) ----------------
__global__ void deg_init_all(float* deg) {
    int i = blockIdx.x * blockDim.x + threadIdx.x;
    if (i < MTOT) deg[i] = 1.0f;  // self loop
}
__global__ void deg_acc_all(float* deg, const int* __restrict__ edge_index,
                            const float* __restrict__ ew) {
    int t = blockIdx.y;
    int e = blockIdx.x * blockDim.x + threadIdx.x;
    if (e < E_) {
        const int* dst = edge_index + (size_t)t * 2 * E_ + E_;
        atomicAdd(&deg[t * N_ + dst[e]], ew[(size_t)t * E_ + e]);
    }
}
__global__ void dinv_all(float* deg) {
    int i = blockIdx.x * blockDim.x + threadIdx.x;
    if (i < MTOT) deg[i] = rsqrtf(deg[i]);
}

// ---------------- tf32 tensor-core GEMM (3xTF32 decomposition) ----------------
__device__ __forceinline__ void mma_tf32(float* c, unsigned a0, unsigned a1,
                                         unsigned a2, unsigned a3,
                                         unsigned b0, unsigned b1) {
    asm volatile(
        "mma.sync.aligned.m16n8k8.row.col.f32.tf32.tf32.f32 "
        "{%0,%1,%2,%3}, {%4,%5,%6,%7}, {%8,%9}, {%0,%1,%2,%3};"
        : "+f"(c[0]), "+f"(c[1]), "+f"(c[2]), "+f"(c[3])
        : "r"(a0), "r"(a1), "r"(a2), "r"(a3), "r"(b0), "r"(b1));
}
__device__ __forceinline__ void split_tf32(float f, unsigned& hi, unsigned& lo) {
    unsigned u = __float_as_uint(f) & 0xFFFFE000u;
    hi = u;
    lo = __float_as_uint(f - __uint_as_float(u));
}

// C[M x 64] = act(A[M x K]) @ W[64 x K]^T
// EPI 0: hw = C ; hout = C * dinv[row]^2
// EPI 1: C += ebias ; scatter rows to tgt via gidx: tgt[(gidx[t,n]*T + t)*64 + col]
template <int K, int EPI>
__global__ void __launch_bounds__(256, 2)
gemm_tc_k(const float* __restrict__ A, const float* __restrict__ Wsrc,
          const float* __restrict__ abias,
          const float* __restrict__ dinv, float* __restrict__ hw, float* __restrict__ hout,
          const float* __restrict__ ebias, const int* __restrict__ gidx,
          float* __restrict__ tgt) {
    constexpr int BM = 128, BK = 32;
    constexpr int NT = K / BK;
    constexpr int WPAD = K + 4;   // mod 32 == 4 -> conflict-free frag loads
    constexpr int APAD = BK + 4;  // 36

    extern __shared__ float sm[];
    float* Wsh = sm;                  // 64 * WPAD
    float* Ash = sm + 64 * WPAD;      // 2 * BM * APAD

    const int tid = threadIdx.x;
    const int wid = tid >> 5, lane = tid & 31;
    const int warp_m = wid & 3, warp_n = wid >> 2;   // 4 x 2 warps
    const int lg = lane >> 2, lt = lane & 3;         // group / thread-in-group
    const long long row0 = (long long)blockIdx.x * BM;

    // load full W tile (64 x K) once
    for (int i = tid * 4; i < 64 * K; i += 256 * 4) {
        int n = i / K, k = i % K;
        float4 w = *(const float4*)(Wsrc + n * K + k);
        *(float4*)(Wsh + n * WPAD + k) = w;
    }

    // A chunk staging (global -> regs -> smem), bias+relu fused on load
    float4 areg[4];
    auto lda = [&](int kt) {
#pragma unroll
        for (int it = 0; it < 4; it++) {
            int idx = it * 256 + tid;
            int r = idx >> 3, kq = idx & 7;
            long long grow = row0 + r;
            float4 v = make_float4(0.f, 0.f, 0.f, 0.f);
            if (grow < MTOT) {
                v = *(const float4*)(A + grow * K + kt * BK + kq * 4);
                if (abias) {
                    float4 b = *(const float4*)(abias + kt * BK + kq * 4);
                    v.x = fmaxf(v.x + b.x, 0.f);
                    v.y = fmaxf(v.y + b.y, 0.f);
                    v.z = fmaxf(v.z + b.z, 0.f);
                    v.w = fmaxf(v.w + b.w, 0.f);
                }
            }
            areg[it] = v;
        }
    };
    auto sts = [&](int buf) {
        float* dst = Ash + buf * BM * APAD;
#pragma unroll
        for (int it = 0; it < 4; it++) {
            int idx = it * 256 + tid;
            int r = idx >> 3, kq = idx & 7;
            *(float4*)(dst + r * APAD + kq * 4) = areg[it];
        }
    };

    float c[2][4][4];
#pragma unroll
    for (int mt = 0; mt < 2; mt++)
#pragma unroll
        for (int nt = 0; nt < 4; nt++)
#pragma unroll
            for (int i = 0; i < 4; i++) c[mt][nt][i] = 0.f;

    lda(0);
    sts(0);

    for (int kt = 0; kt < NT; kt++) {
        __syncthreads();
        if (kt + 1 < NT) lda(kt + 1);
        const float* As = Ash + (kt & 1) * BM * APAD;
#pragma unroll
        for (int ks = 0; ks < 4; ks++) {
            const int k0 = ks * 8 + lt;
            unsigned ahi[2][4], alo[2][4];
#pragma unroll
            for (int mt = 0; mt < 2; mt++) {
                int ar = warp_m * 32 + mt * 16 + lg;
                float f0 = As[ar * APAD + k0];
                float f1 = As[(ar + 8) * APAD + k0];
                float f2 = As[ar * APAD + k0 + 4];
                float f3 = As[(ar + 8) * APAD + k0 + 4];
                split_tf32(f0, ahi[mt][0], alo[mt][0]);
                split_tf32(f1, ahi[mt][1], alo[mt][1]);
                split_tf32(f2, ahi[mt][2], alo[mt][2]);
                split_tf32(f3, ahi[mt][3], alo[mt][3]);
            }
            unsigned bhi[4][2], blo[4][2];
#pragma unroll
            for (int nt = 0; nt < 4; nt++) {
                int bn = warp_n * 32 + nt * 8 + lg;
                float g0 = Wsh[bn * WPAD + kt * BK + k0];
                float g1 = Wsh[bn * WPAD + kt * BK + k0 + 4];
                split_tf32(g0, bhi[nt][0], blo[nt][0]);
                split_tf32(g1, bhi[nt][1], blo[nt][1]);
            }
#pragma unroll
            for (int mt = 0; mt < 2; mt++)
#pragma unroll
                for (int nt = 0; nt < 4; nt++) {
                    mma_tf32(c[mt][nt], ahi[mt][0], ahi[mt][1], ahi[mt][2], ahi[mt][3],
                             bhi[nt][0], bhi[nt][1]);
                    mma_tf32(c[mt][nt], alo[mt][0], alo[mt][1], alo[mt][2], alo[mt][3],
                             bhi[nt][0], bhi[nt][1]);
                    mma_tf32(c[mt][nt], ahi[mt][0], ahi[mt][1], ahi[mt][2], ahi[mt][3],
                             blo[nt][0], blo[nt][1]);
                }
        }
        if (kt + 1 < NT) sts((kt + 1) & 1);
    }

    // epilogue
#pragma unroll
    for (int mt = 0; mt < 2; mt++) {
        long long r_lo = row0 + warp_m * 32 + mt * 16 + lg;
        long long r_hi = r_lo + 8;
#pragma unroll
        for (int half = 0; half < 2; half++) {
            long long r = half ? r_hi : r_lo;
            if (r >= MTOT) continue;
            if (EPI == 0) {
                float di = __ldg(dinv + r);
                float di2 = di * di;
#pragma unroll
                for (int nt = 0; nt < 4; nt++) {
                    int col = warp_n * 32 + nt * 8 + 2 * lt;
                    float v0 = c[mt][nt][half * 2 + 0];
                    float v1 = c[mt][nt][half * 2 + 1];
                    *(float2*)(hw + r * 64 + col) = make_float2(v0, v1);
                    *(float2*)(hout + r * 64 + col) = make_float2(v0 * di2, v1 * di2);
                }
            } else {
                unsigned rr = (unsigned)r;
                unsigned t = rr / (unsigned)N_;
                unsigned n = rr - t * (unsigned)N_;
                int ridx = __ldg(gidx + (size_t)t * R_ + n);
                float* base = tgt + ((size_t)ridx * T_ + t) * 64;
#pragma unroll
                for (int nt = 0; nt < 4; nt++) {
                    int col = warp_n * 32 + nt * 8 + 2 * lt;
                    float2 b = *(const float2*)(ebias + col);
                    float v0 = c[mt][nt][half * 2 + 0] + b.x;
                    float v1 = c[mt][nt][half * 2 + 1] + b.y;
                    *(float2*)(base + col) = make_float2(v0, v1);
                }
            }
        }
    }
}

// ---------------- edge aggregation (batched over T) ----------------
__global__ void agg_all_k(const int* __restrict__ edge_index, const float* __restrict__ ew_all,
                          const float* __restrict__ dinv, const float* __restrict__ hw,
                          float* __restrict__ out) {
    int t = blockIdx.y;
    int tIdx = blockIdx.x * blockDim.x + threadIdx.x;
    int e = tIdx >> 3, sub = tIdx & 7;
    if (e >= E_) return;
    const int* src = edge_index + (size_t)t * 2 * E_;
    const int* dst = src + E_;
    int s = __ldg(src + e), d = __ldg(dst + e);
    float w = __ldg(ew_all + (size_t)t * E_ + e);
    float c = __ldg(dinv + t * N_ + s) * w * __ldg(dinv + t * N_ + d);
    const float4* hp = (const float4*)(hw + ((size_t)t * N_ + s) * 64) + 2 * sub;
    float4 a = __ldg(hp), b = __ldg(hp + 1);
    float* op = out + ((size_t)t * N_ + d) * 64 + 8 * sub;
    asm volatile("red.global.add.v4.f32 [%0], {%1,%2,%3,%4};"
                 :: "l"(op), "f"(c * a.x), "f"(c * a.y), "f"(c * a.z), "f"(c * a.w) : "memory");
    asm volatile("red.global.add.v4.f32 [%0], {%1,%2,%3,%4};"
                 :: "l"(op + 4), "f"(c * b.x), "f"(c * b.y), "f"(c * b.z), "f"(c * b.w) : "memory");
}

// ---------------- te9: relu(h2[t=9] + b2) scattered by gidx ----------------
__global__ void te9_k(const float* __restrict__ h2, const float* __restrict__ b2,
                      const int* __restrict__ gidx, float* __restrict__ te9) {
    int idx = blockIdx.x * blockDim.x + threadIdx.x;
    if (idx >= N_ * D_) return;
    int n = idx >> 6, c = idx & 63;
    float v = fmaxf(h2[((size_t)9 * N_ + n) * 64 + c] + b2[c], 0.f);
    te9[(size_t)__ldg(gidx + (size_t)9 * R_ + n) * 64 + c] = v;
}

// ---------------- tail ----------------
#define TAIL_WARPS 4
#define TAIL_SMEM  ((12288 + 704 + TAIL_WARPS * 1456) * 4)

__device__ __forceinline__ float warp_sum(float v) {
#pragma unroll
    for (int off = 16; off; off >>= 1) v += __shfl_xor_sync(0xffffffffu, v, off);
    return v;
}

__global__ void tail_k(const float* __restrict__ inW, const float* __restrict__ inB,
                       const float* __restrict__ outW, const float* __restrict__ outB,
                       const float* __restrict__ w1, const float* __restrict__ w2,
                       const float* __restrict__ w3, const float* __restrict__ w4,
                       const float* __restrict__ ln1g, const float* __restrict__ ln1b,
                       const float* __restrict__ ln2g, const float* __restrict__ ln2b,
                       const float* __restrict__ fcW, const float* __restrict__ fcB,
                       const float* __restrict__ te9, const float* __restrict__ gK,
                       const float* __restrict__ gV, float* __restrict__ out) {
    extern __shared__ float sh[];
    float* Wq = sh;
    float* Wo = sh + 4096;
    float* Wf = sh + 8192;
    float* cv = sh + 12288;

    int tid = threadIdx.x;
    for (int i = tid; i < 4096; i += 128) {
        int k = i >> 6, j = i & 63;
        Wq[i] = inW[j * 64 + k];
        Wo[i] = outW[j * 64 + k];
        Wf[i] = fcW[j * 64 + k];
    }
    if (tid < 64) {
        cv[tid]       = inB[tid];
        cv[64 + tid]  = outB[tid];
        cv[128 + tid] = fcB[tid];
        cv[192 + tid] = w1[(T_ - 1) * 64 + tid];
        cv[256 + tid] = w2[(T_ - 1) * 64 + tid];
        cv[320 + tid] = ln1g[tid];
        cv[384 + tid] = ln1b[tid];
        cv[448 + tid] = w3[tid];
        cv[512 + tid] = w4[tid];
        cv[576 + tid] = ln2g[tid];
        cv[640 + tid] = ln2b[tid];
    }
    __syncthreads();

    int warp = tid >> 5, lane = tid & 31;
    float* wb   = cv + 704 + warp * 1456;
    float* pvec = wb;
    float* pq   = wb + 64;
    float* kb   = wb + 128;
    float* vb   = wb + 768;
    float* sc   = wb + 1408;

    int gw = blockIdx.x * TAIL_WARPS + warp;
    int nw = gridDim.x * TAIL_WARPS;

    for (int r = gw; r < R_; r += nw) {
        pvec[lane]      = te9[(size_t)r * 64 + lane];
        pvec[lane + 32] = te9[(size_t)r * 64 + lane + 32];
        for (int i = lane; i < 640; i += 32) {
            kb[i] = gK[(size_t)r * 640 + i];
            vb[i] = gV[(size_t)r * 640 + i];
        }
        __syncwarp();

        float q0 = cv[lane], q1 = cv[lane + 32];
        for (int k = 0; k < 64; k++) {
            float xv = pvec[k];
            q0 = fmaf(xv, Wq[k * 64 + lane], q0);
            q1 = fmaf(xv, Wq[k * 64 + lane + 32], q1);
        }
        pq[lane] = q0; pq[lane + 32] = q1;
        __syncwarp();

        for (int p = lane; p < H_ * T_; p += 32) {
            int h = p / T_, tt = p - h * T_;
            const float* qh = pq + h * 16;
            const float* kh = kb + tt * 64 + h * 16;
            float s = 0.f;
#pragma unroll
            for (int d = 0; d < 16; d++) s = fmaf(qh[d], kh[d], s);
            sc[p] = s * 0.25f;
        }
        __syncwarp();

        if (lane < H_) {
            float mx = -1e30f;
#pragma unroll
            for (int tt = 0; tt < T_; tt++) mx = fmaxf(mx, sc[lane * T_ + tt]);
            float sm = 0.f;
#pragma unroll
            for (int tt = 0; tt < T_; tt++) {
                float ev = __expf(sc[lane * T_ + tt] - mx);
                sc[lane * T_ + tt] = ev; sm += ev;
            }
            float inv = 1.f / sm;
#pragma unroll
            for (int tt = 0; tt < T_; tt++) sc[lane * T_ + tt] *= inv;
        }
        __syncwarp();

        int h0 = lane >> 4, h1 = (lane + 32) >> 4;
        float a0 = 0.f, a1 = 0.f;
#pragma unroll
        for (int tt = 0; tt < T_; tt++) {
            a0 = fmaf(sc[h0 * T_ + tt], vb[tt * 64 + lane], a0);
            a1 = fmaf(sc[h1 * T_ + tt], vb[tt * 64 + lane + 32], a1);
        }
        pq[lane] = a0; pq[lane + 32] = a1;
        __syncwarp();

        float o0 = cv[64 + lane], o1 = cv[64 + lane + 32];
        for (int k = 0; k < 64; k++) {
            float xv = pq[k];
            o0 = fmaf(xv, Wo[k * 64 + lane], o0);
            o1 = fmaf(xv, Wo[k * 64 + lane + 32], o1);
        }

        float y0 = cv[192 + lane] * pvec[lane] + cv[256 + lane] * o0;
        float y1 = cv[192 + lane + 32] * pvec[lane + 32] + cv[256 + lane + 32] * o1;
        float mu = warp_sum(y0 + y1) * (1.f / 64.f);
        float d0 = y0 - mu, d1 = y1 - mu;
        float var = warp_sum(d0 * d0 + d1 * d1) * (1.f / 64.f);
        float rs = rsqrtf(var + 1e-5f);
        float f0 = d0 * rs * cv[320 + lane] + cv[384 + lane];
        float f1 = d1 * rs * cv[320 + lane + 32] + cv[384 + lane + 32];
        __syncwarp();
        pvec[lane] = f0; pvec[lane + 32] = f1;
        __syncwarp();

        float u0 = cv[128 + lane], u1 = cv[128 + lane + 32];
        for (int k = 0; k < 64; k++) {
            float xv = pvec[k];
            u0 = fmaf(xv, Wf[k * 64 + lane], u0);
            u1 = fmaf(xv, Wf[k * 64 + lane + 32], u1);
        }
        float z0 = cv[448 + lane] * f0 + cv[512 + lane] * u0;
        float z1 = cv[448 + lane + 32] * f1 + cv[512 + lane + 32] * u1;
        float mu2 = warp_sum(z0 + z1) * (1.f / 64.f);
        float e0 = z0 - mu2, e1 = z1 - mu2;
        float var2 = warp_sum(e0 * e0 + e1 * e1) * (1.f / 64.f);
        float rs2 = rsqrtf(var2 + 1e-5f);
        out[(size_t)r * 64 + lane]      = e0 * rs2 * cv[576 + lane] + cv[640 + lane];
        out[(size_t)r * 64 + lane + 32] = e1 * rs2 * cv[576 + lane + 32] + cv[640 + lane + 32];
        __syncwarp();
    }
}

// ---------------- launch ----------------
extern "C" void kernel_launch(void* const* d_in, const int* in_sizes, int n_in,
                              void* d_out, int out_size) {
    const float* x          = (const float*)d_in[0];
    const int*   edge_index = (const int*)  d_in[1];
    const float* edge_weight= (const float*)d_in[2];
    const int*   global_idx = (const int*)  d_in[3];
    const float* gcn1_w     = (const float*)d_in[4];
    const float* gcn1_b     = (const float*)d_in[5];
    const float* gcn2_w     = (const float*)d_in[6];
    const float* gcn2_b     = (const float*)d_in[7];
    const float* in_proj_w  = (const float*)d_in[8];
    const float* in_proj_b  = (const float*)d_in[9];
    const float* out_proj_w = (const float*)d_in[10];
    const float* out_proj_b = (const float*)d_in[11];
    const float* w1         = (const float*)d_in[12];
    const float* w2         = (const float*)d_in[13];
    const float* w3         = (const float*)d_in[14];
    const float* w4         = (const float*)d_in[15];
    const float* ln1_g      = (const float*)d_in[16];
    const float* ln1_b      = (const float*)d_in[17];
    const float* ln2_g      = (const float*)d_in[18];
    const float* ln2_b      = (const float*)d_in[19];
    const float* fc_w       = (const float*)d_in[20];
    const float* fc_b       = (const float*)d_in[21];
    float* out = (float*)d_out;

    float *deg, *hw, *h1, *h2, *gk, *gv, *te9;
    cudaGetSymbolAddress((void**)&deg, g_deg);
    cudaGetSymbolAddress((void**)&hw,  g_hw);
    cudaGetSymbolAddress((void**)&h1,  g_h1);
    cudaGetSymbolAddress((void**)&h2,  g_h2);
    cudaGetSymbolAddress((void**)&gk,  g_k);
    cudaGetSymbolAddress((void**)&gv,  g_v);
    cudaGetSymbolAddress((void**)&te9, g_te9);

    // smem: W(64*(K+4)) + double-buffered A(2*128*36)
    const int SM_TC1 = (64 * (128 + 4) + 2 * 128 * 36) * 4;  // 70656
    const int SM_TC2 = (64 * (64 + 4)  + 2 * 128 * 36) * 4;  // 54272
    cudaFuncSetAttribute((const void*)gemm_tc_k<128, 0>,
                         cudaFuncAttributeMaxDynamicSharedMemorySize, SM_TC1);
    cudaFuncSetAttribute((const void*)gemm_tc_k<64, 0>,
                         cudaFuncAttributeMaxDynamicSharedMemorySize, SM_TC2);
    cudaFuncSetAttribute((const void*)gemm_tc_k<64, 1>,
                         cudaFuncAttributeMaxDynamicSharedMemorySize, SM_TC2);
    cudaFuncSetAttribute(tail_k, cudaFuncAttributeMaxDynamicSharedMemorySize, TAIL_SMEM);

    const int NB_M  = (MTOT + 255) / 256;
    const int NB_G  = (MTOT + 127) / 128;    // 3907 blocks, BM=128
    const dim3 GB_E((E_ + 255) / 256, T_);
    const dim3 GB_A((E_ * 8 + 255) / 256, T_);

    deg_init_all<<<NB_M, 256>>>(deg);
    deg_acc_all <<<GB_E, 256>>>(deg, edge_index, edge_weight);
    dinv_all    <<<NB_M, 256>>>(deg);

    // layer 1: GEMM (tf32 TC) + edge aggregation
    gemm_tc_k<128, 0><<<NB_G, 256, SM_TC1>>>(x, gcn1_w, nullptr,
                                             deg, hw, h1, nullptr, nullptr, nullptr);
    agg_all_k<<<GB_A, 256>>>(edge_index, edge_weight, deg, hw, h1);

    // layer 2: GEMM with fused relu(h1+b1) + edge aggregation
    gemm_tc_k<64, 0><<<NB_G, 256, SM_TC2>>>(h1, gcn2_w, gcn1_b,
                                            deg, hw, h2, nullptr, nullptr, nullptr);
    agg_all_k<<<GB_A, 256>>>(edge_index, edge_weight, deg, hw, h2);

    // K and V projections (fused relu(h2+b2), bias + permutation scatter)
    gemm_tc_k<64, 1><<<NB_G, 256, SM_TC2>>>(h2, in_proj_w + 64 * 64, gcn2_b,
                                            nullptr, nullptr, nullptr,
                                            in_proj_b + 64, global_idx, gk);
    gemm_tc_k<64, 1><<<NB_G, 256, SM_TC2>>>(h2, in_proj_w + 128 * 64, gcn2_b,
                                            nullptr, nullptr, nullptr,
                                            in_proj_b + 128, global_idx, gv);

    te9_k<<<(N_ * D_ + 255) / 256, 256>>>(h2, gcn2_b, global_idx, te9);

    tail_k<<<296, 128, TAIL_SMEM>>>(in_proj_w, in_proj_b, out_proj_w, out_proj_b,
                                    w1, w2, w3, w4, ln1_g, ln1_b, ln2_g, ln2_b,
                                    fc_w, fc_b, te9, gk, gv, out);
}

// round 5
// speedup vs baseline: 2.4774x; 1.2663x over previous
#include <cuda_runtime.h>
#include <cstdint>

#define T_   10
#define N_   50000
#define R_   50000
#define DIN_ 128
#define D_   64
#define H_   4
#define E_   400000
#define MTOT (T_ * N_)   // 500000
#define ETOT (T_ * E_)   // 4000000
#define SCAN_BLK 4096
#define NSCAN ((MTOT + SCAN_BLK - 1) / SCAN_BLK)   // 123

// ---------------- scratch ----------------
__device__ float g_deg[(size_t)MTOT];
__device__ int   g_cnt[(size_t)MTOT];
__device__ int   g_offs[(size_t)MTOT];
__device__ int   g_offw[(size_t)MTOT];
__device__ int   g_bsum[256];
__device__ int2  g_bucket[(size_t)ETOT];
__device__ float g_hw [(size_t)MTOT * D_];
__device__ float g_h1 [(size_t)MTOT * D_];
__device__ float g_h2 [(size_t)MTOT * D_];
__device__ float g_k  [(size_t)R_ * T_ * D_];
__device__ float g_v  [(size_t)R_ * T_ * D_];
__device__ float g_te9[(size_t)R_ * D_];

// ---------------- init / degree / count ----------------
__global__ void init_k(float* deg, int* cnt) {
    int i = blockIdx.x * blockDim.x + threadIdx.x;
    if (i < MTOT) { deg[i] = 1.0f; cnt[i] = 0; }
}
__global__ void pass1_k(float* deg, int* cnt, const int* __restrict__ edge_index,
                        const float* __restrict__ ew) {
    int t = blockIdx.y;
    int e = blockIdx.x * blockDim.x + threadIdx.x;
    if (e < E_) {
        int d = __ldg(edge_index + (size_t)t * 2 * E_ + E_ + e);
        atomicAdd(&deg[t * N_ + d], __ldg(ew + (size_t)t * E_ + e));
        atomicAdd(&cnt[t * N_ + d], 1);
    }
}
__global__ void dinv_all(float* deg) {
    int i = blockIdx.x * blockDim.x + threadIdx.x;
    if (i < MTOT) deg[i] = rsqrtf(deg[i]);
}

// ---------------- exclusive scan of cnt -> offs ----------------
__global__ void scan1_k(const int* __restrict__ cnt, int* __restrict__ offs,
                        int* __restrict__ bsum) {
    __shared__ int ts[256];
    int b = blockIdx.x, tid = threadIdx.x;
    int base = b * SCAN_BLK + tid * 16;
    int v[16]; int s = 0;
#pragma unroll
    for (int i = 0; i < 16; i++) {
        int idx = base + i;
        v[i] = (idx < MTOT) ? cnt[idx] : 0;
        s += v[i];
    }
    ts[tid] = s;
    __syncthreads();
    for (int off = 1; off < 256; off <<= 1) {
        int x = (tid >= off) ? ts[tid - off] : 0;
        __syncthreads();
        ts[tid] += x;
        __syncthreads();
    }
    int excl = ts[tid] - s;
    if (tid == 255) bsum[b] = ts[255];
    int run = excl;
#pragma unroll
    for (int i = 0; i < 16; i++) {
        int idx = base + i;
        if (idx < MTOT) offs[idx] = run;
        run += v[i];
    }
}
__global__ void scan2_k(int* bsum, int nb) {
    if (threadIdx.x == 0) {
        int run = 0;
        for (int i = 0; i < nb; i++) { int v = bsum[i]; bsum[i] = run; run += v; }
    }
}
__global__ void scan3_k(int* __restrict__ offs, int* __restrict__ offw,
                        const int* __restrict__ bsum) {
    int i = blockIdx.x * blockDim.x + threadIdx.x;
    if (i < MTOT) {
        int v = offs[i] + bsum[i >> 12];
        offs[i] = v;
        offw[i] = v;
    }
}

// ---------------- scatter edges into CSR buckets ----------------
__global__ void scatter_k(const int* __restrict__ edge_index, const float* __restrict__ ew,
                          const float* __restrict__ dinv, int* __restrict__ offw,
                          int2* __restrict__ bucket) {
    int t = blockIdx.y;
    int e = blockIdx.x * blockDim.x + threadIdx.x;
    if (e >= E_) return;
    const int* src = edge_index + (size_t)t * 2 * E_;
    int s = __ldg(src + e), d = __ldg(src + E_ + e);
    float w = __ldg(ew + (size_t)t * E_ + e);
    float c = __ldg(dinv + t * N_ + s) * w * __ldg(dinv + t * N_ + d);
    int pos = atomicAdd(&offw[t * N_ + d], 1);
    bucket[pos] = make_int2(s, __float_as_int(c));
}

// ---------------- gather aggregation: out[n] = hw[n]*dinv^2 + sum c*hw[src] ----------------
__global__ void agg2_k(const int2* __restrict__ bucket, const int* __restrict__ offs,
                       const int* __restrict__ offw, const float* __restrict__ dinv,
                       const float* __restrict__ hw, float* __restrict__ out) {
    int idx = blockIdx.x * blockDim.x + threadIdx.x;
    int node = idx >> 3, sub = idx & 7;
    if (node >= MTOT) return;
    long long tb = (long long)(node / N_) * N_;
    float di = __ldg(dinv + node);
    float s2 = di * di;
    const float4* hp = (const float4*)(hw + (size_t)node * 64) + 2 * sub;
    float4 a = __ldg(hp), b = __ldg(hp + 1);
    float4 acc0 = make_float4(a.x * s2, a.y * s2, a.z * s2, a.w * s2);
    float4 acc1 = make_float4(b.x * s2, b.y * s2, b.z * s2, b.w * s2);
    int p = __ldg(offs + node), e = __ldg(offw + node);
    for (; p < e; p++) {
        int2 ed = __ldg(bucket + p);
        float c = __int_as_float(ed.y);
        const float4* sp = (const float4*)(hw + (size_t)(tb + ed.x) * 64) + 2 * sub;
        float4 u = __ldg(sp), v = __ldg(sp + 1);
        acc0.x = fmaf(c, u.x, acc0.x); acc0.y = fmaf(c, u.y, acc0.y);
        acc0.z = fmaf(c, u.z, acc0.z); acc0.w = fmaf(c, u.w, acc0.w);
        acc1.x = fmaf(c, v.x, acc1.x); acc1.y = fmaf(c, v.y, acc1.y);
        acc1.z = fmaf(c, v.z, acc1.z); acc1.w = fmaf(c, v.w, acc1.w);
    }
    float4* op = (float4*)(out + (size_t)node * 64) + 2 * sub;
    op[0] = acc0;
    op[1] = acc1;
}

// ---------------- tf32 tensor-core GEMM (3xTF32 decomposition) ----------------
__device__ __forceinline__ void mma_tf32(float* c, unsigned a0, unsigned a1,
                                         unsigned a2, unsigned a3,
                                         unsigned b0, unsigned b1) {
    asm volatile(
        "mma.sync.aligned.m16n8k8.row.col.f32.tf32.tf32.f32 "
        "{%0,%1,%2,%3}, {%4,%5,%6,%7}, {%8,%9}, {%0,%1,%2,%3};"
        : "+f"(c[0]), "+f"(c[1]), "+f"(c[2]), "+f"(c[3])
        : "r"(a0), "r"(a1), "r"(a2), "r"(a3), "r"(b0), "r"(b1));
}
__device__ __forceinline__ void split_tf32(float f, unsigned& hi, unsigned& lo) {
    unsigned u = __float_as_uint(f) & 0xFFFFE000u;
    hi = u;
    lo = __float_as_uint(f - __uint_as_float(u));
}

// C[M x 64] = act(A[M x K]) @ W[64 x K]^T
// EPI 0: hw = C
// EPI 1: C += ebias ; scatter rows to tgt via gidx: tgt[(gidx[t,n]*T + t)*64 + col]
template <int K, int EPI>
__global__ void __launch_bounds__(256, 2)
gemm_tc_k(const float* __restrict__ A, const float* __restrict__ Wsrc,
          const float* __restrict__ abias,
          float* __restrict__ hw,
          const float* __restrict__ ebias, const int* __restrict__ gidx,
          float* __restrict__ tgt) {
    constexpr int BM = 128, BK = 32;
    constexpr int NT = K / BK;
    constexpr int WPAD = K + 4;
    constexpr int APAD = BK + 4;

    extern __shared__ float sm[];
    float* Wsh = sm;
    float* Ash = sm + 64 * WPAD;

    const int tid = threadIdx.x;
    const int wid = tid >> 5, lane = tid & 31;
    const int warp_m = wid & 3, warp_n = wid >> 2;
    const int lg = lane >> 2, lt = lane & 3;
    const long long row0 = (long long)blockIdx.x * BM;

    for (int i = tid * 4; i < 64 * K; i += 256 * 4) {
        int n = i / K, k = i % K;
        float4 w = *(const float4*)(Wsrc + n * K + k);
        *(float4*)(Wsh + n * WPAD + k) = w;
    }

    float4 areg[4];
    auto lda = [&](int kt) {
#pragma unroll
        for (int it = 0; it < 4; it++) {
            int idx = it * 256 + tid;
            int r = idx >> 3, kq = idx & 7;
            long long grow = row0 + r;
            float4 v = make_float4(0.f, 0.f, 0.f, 0.f);
            if (grow < MTOT) {
                v = *(const float4*)(A + grow * K + kt * BK + kq * 4);
                if (abias) {
                    float4 b = *(const float4*)(abias + kt * BK + kq * 4);
                    v.x = fmaxf(v.x + b.x, 0.f);
                    v.y = fmaxf(v.y + b.y, 0.f);
                    v.z = fmaxf(v.z + b.z, 0.f);
                    v.w = fmaxf(v.w + b.w, 0.f);
                }
            }
            areg[it] = v;
        }
    };
    auto sts = [&](int buf) {
        float* dst = Ash + buf * BM * APAD;
#pragma unroll
        for (int it = 0; it < 4; it++) {
            int idx = it * 256 + tid;
            int r = idx >> 3, kq = idx & 7;
            *(float4*)(dst + r * APAD + kq * 4) = areg[it];
        }
    };

    float c[2][4][4];
#pragma unroll
    for (int mt = 0; mt < 2; mt++)
#pragma unroll
        for (int nt = 0; nt < 4; nt++)
#pragma unroll
            for (int i = 0; i < 4; i++) c[mt][nt][i] = 0.f;

    lda(0);
    sts(0);

    for (int kt = 0; kt < NT; kt++) {
        __syncthreads();
        if (kt + 1 < NT) lda(kt + 1);
        const float* As = Ash + (kt & 1) * BM * APAD;
#pragma unroll
        for (int ks = 0; ks < 4; ks++) {
            const int k0 = ks * 8 + lt;
            unsigned ahi[2][4], alo[2][4];
#pragma unroll
            for (int mt = 0; mt < 2; mt++) {
                int ar = warp_m * 32 + mt * 16 + lg;
                float f0 = As[ar * APAD + k0];
                float f1 = As[(ar + 8) * APAD + k0];
                float f2 = As[ar * APAD + k0 + 4];
                float f3 = As[(ar + 8) * APAD + k0 + 4];
                split_tf32(f0, ahi[mt][0], alo[mt][0]);
                split_tf32(f1, ahi[mt][1], alo[mt][1]);
                split_tf32(f2, ahi[mt][2], alo[mt][2]);
                split_tf32(f3, ahi[mt][3], alo[mt][3]);
            }
            unsigned bhi[4][2], blo[4][2];
#pragma unroll
            for (int nt = 0; nt < 4; nt++) {
                int bn = warp_n * 32 + nt * 8 + lg;
                float g0 = Wsh[bn * WPAD + kt * BK + k0];
                float g1 = Wsh[bn * WPAD + kt * BK + k0 + 4];
                split_tf32(g0, bhi[nt][0], blo[nt][0]);
                split_tf32(g1, bhi[nt][1], blo[nt][1]);
            }
#pragma unroll
            for (int mt = 0; mt < 2; mt++)
#pragma unroll
                for (int nt = 0; nt < 4; nt++) {
                    mma_tf32(c[mt][nt], ahi[mt][0], ahi[mt][1], ahi[mt][2], ahi[mt][3],
                             bhi[nt][0], bhi[nt][1]);
                    mma_tf32(c[mt][nt], alo[mt][0], alo[mt][1], alo[mt][2], alo[mt][3],
                             bhi[nt][0], bhi[nt][1]);
                    mma_tf32(c[mt][nt], ahi[mt][0], ahi[mt][1], ahi[mt][2], ahi[mt][3],
                             blo[nt][0], blo[nt][1]);
                }
        }
        if (kt + 1 < NT) sts((kt + 1) & 1);
    }

#pragma unroll
    for (int mt = 0; mt < 2; mt++) {
        long long r_lo = row0 + warp_m * 32 + mt * 16 + lg;
#pragma unroll
        for (int half = 0; half < 2; half++) {
            long long r = r_lo + half * 8;
            if (r >= MTOT) continue;
            if (EPI == 0) {
#pragma unroll
                for (int nt = 0; nt < 4; nt++) {
                    int col = warp_n * 32 + nt * 8 + 2 * lt;
                    *(float2*)(hw + r * 64 + col) =
                        make_float2(c[mt][nt][half * 2 + 0], c[mt][nt][half * 2 + 1]);
                }
            } else {
                unsigned rr = (unsigned)r;
                unsigned t = rr / (unsigned)N_;
                unsigned n = rr - t * (unsigned)N_;
                int ridx = __ldg(gidx + (size_t)t * R_ + n);
                float* base = tgt + ((size_t)ridx * T_ + t) * 64;
#pragma unroll
                for (int nt = 0; nt < 4; nt++) {
                    int col = warp_n * 32 + nt * 8 + 2 * lt;
                    float2 b = *(const float2*)(ebias + col);
                    *(float2*)(base + col) =
                        make_float2(c[mt][nt][half * 2 + 0] + b.x,
                                    c[mt][nt][half * 2 + 1] + b.y);
                }
            }
        }
    }
}

// ---------------- te9: relu(h2[t=9] + b2) scattered by gidx ----------------
__global__ void te9_k(const float* __restrict__ h2, const float* __restrict__ b2,
                      const int* __restrict__ gidx, float* __restrict__ te9) {
    int idx = blockIdx.x * blockDim.x + threadIdx.x;
    if (idx >= N_ * D_) return;
    int n = idx >> 6, c = idx & 63;
    float v = fmaxf(h2[((size_t)9 * N_ + n) * 64 + c] + b2[c], 0.f);
    te9[(size_t)__ldg(gidx + (size_t)9 * R_ + n) * 64 + c] = v;
}

// ---------------- tail ----------------
#define TAIL_WARPS 4
#define TAIL_SMEM  ((12288 + 704 + TAIL_WARPS * 1456) * 4)

__device__ __forceinline__ float warp_sum(float v) {
#pragma unroll
    for (int off = 16; off; off >>= 1) v += __shfl_xor_sync(0xffffffffu, v, off);
    return v;
}

__global__ void tail_k(const float* __restrict__ inW, const float* __restrict__ inB,
                       const float* __restrict__ outW, const float* __restrict__ outB,
                       const float* __restrict__ w1, const float* __restrict__ w2,
                       const float* __restrict__ w3, const float* __restrict__ w4,
                       const float* __restrict__ ln1g, const float* __restrict__ ln1b,
                       const float* __restrict__ ln2g, const float* __restrict__ ln2b,
                       const float* __restrict__ fcW, const float* __restrict__ fcB,
                       const float* __restrict__ te9, const float* __restrict__ gK,
                       const float* __restrict__ gV, float* __restrict__ out) {
    extern __shared__ float sh[];
    float* Wq = sh;
    float* Wo = sh + 4096;
    float* Wf = sh + 8192;
    float* cv = sh + 12288;

    int tid = threadIdx.x;
    for (int i = tid; i < 4096; i += 128) {
        int k = i >> 6, j = i & 63;
        Wq[i] = inW[j * 64 + k];
        Wo[i] = outW[j * 64 + k];
        Wf[i] = fcW[j * 64 + k];
    }
    if (tid < 64) {
        cv[tid]       = inB[tid];
        cv[64 + tid]  = outB[tid];
        cv[128 + tid] = fcB[tid];
        cv[192 + tid] = w1[(T_ - 1) * 64 + tid];
        cv[256 + tid] = w2[(T_ - 1) * 64 + tid];
        cv[320 + tid] = ln1g[tid];
        cv[384 + tid] = ln1b[tid];
        cv[448 + tid] = w3[tid];
        cv[512 + tid] = w4[tid];
        cv[576 + tid] = ln2g[tid];
        cv[640 + tid] = ln2b[tid];
    }
    __syncthreads();

    int warp = tid >> 5, lane = tid & 31;
    float* wb   = cv + 704 + warp * 1456;
    float* pvec = wb;
    float* pq   = wb + 64;
    float* kb   = wb + 128;
    float* vb   = wb + 768;
    float* sc   = wb + 1408;

    int gw = blockIdx.x * TAIL_WARPS + warp;
    int nw = gridDim.x * TAIL_WARPS;

    for (int r = gw; r < R_; r += nw) {
        pvec[lane]      = te9[(size_t)r * 64 + lane];
        pvec[lane + 32] = te9[(size_t)r * 64 + lane + 32];
        for (int i = lane; i < 640; i += 32) {
            kb[i] = gK[(size_t)r * 640 + i];
            vb[i] = gV[(size_t)r * 640 + i];
        }
        __syncwarp();

        float q0 = cv[lane], q1 = cv[lane + 32];
        for (int k = 0; k < 64; k++) {
            float xv = pvec[k];
            q0 = fmaf(xv, Wq[k * 64 + lane], q0);
            q1 = fmaf(xv, Wq[k * 64 + lane + 32], q1);
        }
        pq[lane] = q0; pq[lane + 32] = q1;
        __syncwarp();

        for (int p = lane; p < H_ * T_; p += 32) {
            int h = p / T_, tt = p - h * T_;
            const float* qh = pq + h * 16;
            const float* kh = kb + tt * 64 + h * 16;
            float s = 0.f;
#pragma unroll
            for (int d = 0; d < 16; d++) s = fmaf(qh[d], kh[d], s);
            sc[p] = s * 0.25f;
        }
        __syncwarp();

        if (lane < H_) {
            float mx = -1e30f;
#pragma unroll
            for (int tt = 0; tt < T_; tt++) mx = fmaxf(mx, sc[lane * T_ + tt]);
            float sm = 0.f;
#pragma unroll
            for (int tt = 0; tt < T_; tt++) {
                float ev = __expf(sc[lane * T_ + tt] - mx);
                sc[lane * T_ + tt] = ev; sm += ev;
            }
            float inv = 1.f / sm;
#pragma unroll
            for (int tt = 0; tt < T_; tt++) sc[lane * T_ + tt] *= inv;
        }
        __syncwarp();

        int h0 = lane >> 4, h1 = (lane + 32) >> 4;
        float a0 = 0.f, a1 = 0.f;
#pragma unroll
        for (int tt = 0; tt < T_; tt++) {
            a0 = fmaf(sc[h0 * T_ + tt], vb[tt * 64 + lane], a0);
            a1 = fmaf(sc[h1 * T_ + tt], vb[tt * 64 + lane + 32], a1);
        }
        pq[lane] = a0; pq[lane + 32] = a1;
        __syncwarp();

        float o0 = cv[64 + lane], o1 = cv[64 + lane + 32];
        for (int k = 0; k < 64; k++) {
            float xv = pq[k];
            o0 = fmaf(xv, Wo[k * 64 + lane], o0);
            o1 = fmaf(xv, Wo[k * 64 + lane + 32], o1);
        }

        float y0 = cv[192 + lane] * pvec[lane] + cv[256 + lane] * o0;
        float y1 = cv[192 + lane + 32] * pvec[lane + 32] + cv[256 + lane + 32] * o1;
        float mu = warp_sum(y0 + y1) * (1.f / 64.f);
        float d0 = y0 - mu, d1 = y1 - mu;
        float var = warp_sum(d0 * d0 + d1 * d1) * (1.f / 64.f);
        float rs = rsqrtf(var + 1e-5f);
        float f0 = d0 * rs * cv[320 + lane] + cv[384 + lane];
        float f1 = d1 * rs * cv[320 + lane + 32] + cv[384 + lane + 32];
        __syncwarp();
        pvec[lane] = f0; pvec[lane + 32] = f1;
        __syncwarp();

        float u0 = cv[128 + lane], u1 = cv[128 + lane + 32];
        for (int k = 0; k < 64; k++) {
            float xv = pvec[k];
            u0 = fmaf(xv, Wf[k * 64 + lane], u0);
            u1 = fmaf(xv, Wf[k * 64 + lane + 32], u1);
        }
        float z0 = cv[448 + lane] * f0 + cv[512 + lane] * u0;
        float z1 = cv[448 + lane + 32] * f1 + cv[512 + lane + 32] * u1;
        float mu2 = warp_sum(z0 + z1) * (1.f / 64.f);
        float e0 = z0 - mu2, e1 = z1 - mu2;
        float var2 = warp_sum(e0 * e0 + e1 * e1) * (1.f / 64.f);
        float rs2 = rsqrtf(var2 + 1e-5f);
        out[(size_t)r * 64 + lane]      = e0 * rs2 * cv[576 + lane] + cv[640 + lane];
        out[(size_t)r * 64 + lane + 32] = e1 * rs2 * cv[576 + lane + 32] + cv[640 + lane + 32];
        __syncwarp();
    }
}

// ---------------- launch ----------------
extern "C" void kernel_launch(void* const* d_in, const int* in_sizes, int n_in,
                              void* d_out, int out_size) {
    const float* x          = (const float*)d_in[0];
    const int*   edge_index = (const int*)  d_in[1];
    const float* edge_weight= (const float*)d_in[2];
    const int*   global_idx = (const int*)  d_in[3];
    const float* gcn1_w     = (const float*)d_in[4];
    const float* gcn1_b     = (const float*)d_in[5];
    const float* gcn2_w     = (const float*)d_in[6];
    const float* gcn2_b     = (const float*)d_in[7];
    const float* in_proj_w  = (const float*)d_in[8];
    const float* in_proj_b  = (const float*)d_in[9];
    const float* out_proj_w = (const float*)d_in[10];
    const float* out_proj_b = (const float*)d_in[11];
    const float* w1         = (const float*)d_in[12];
    const float* w2         = (const float*)d_in[13];
    const float* w3         = (const float*)d_in[14];
    const float* w4         = (const float*)d_in[15];
    const float* ln1_g      = (const float*)d_in[16];
    const float* ln1_b      = (const float*)d_in[17];
    const float* ln2_g      = (const float*)d_in[18];
    const float* ln2_b      = (const float*)d_in[19];
    const float* fc_w       = (const float*)d_in[20];
    const float* fc_b       = (const float*)d_in[21];
    float* out = (float*)d_out;

    float *deg, *hw, *h1, *h2, *gk, *gv, *te9;
    int *cnt, *offs, *offw, *bsum;
    int2* bucket;
    cudaGetSymbolAddress((void**)&deg,  g_deg);
    cudaGetSymbolAddress((void**)&cnt,  g_cnt);
    cudaGetSymbolAddress((void**)&offs, g_offs);
    cudaGetSymbolAddress((void**)&offw, g_offw);
    cudaGetSymbolAddress((void**)&bsum, g_bsum);
    cudaGetSymbolAddress((void**)&bucket, g_bucket);
    cudaGetSymbolAddress((void**)&hw,  g_hw);
    cudaGetSymbolAddress((void**)&h1,  g_h1);
    cudaGetSymbolAddress((void**)&h2,  g_h2);
    cudaGetSymbolAddress((void**)&gk,  g_k);
    cudaGetSymbolAddress((void**)&gv,  g_v);
    cudaGetSymbolAddress((void**)&te9, g_te9);

    const int SM_TC1 = (64 * (128 + 4) + 2 * 128 * 36) * 4;  // 70656
    const int SM_TC2 = (64 * (64 + 4)  + 2 * 128 * 36) * 4;  // 54272
    cudaFuncSetAttribute((const void*)gemm_tc_k<128, 0>,
                         cudaFuncAttributeMaxDynamicSharedMemorySize, SM_TC1);
    cudaFuncSetAttribute((const void*)gemm_tc_k<64, 0>,
                         cudaFuncAttributeMaxDynamicSharedMemorySize, SM_TC2);
    cudaFuncSetAttribute((const void*)gemm_tc_k<64, 1>,
                         cudaFuncAttributeMaxDynamicSharedMemorySize, SM_TC2);
    cudaFuncSetAttribute(tail_k, cudaFuncAttributeMaxDynamicSharedMemorySize, TAIL_SMEM);

    const int NB_M  = (MTOT + 255) / 256;
    const int NB_G  = (MTOT + 127) / 128;           // 3907
    const dim3 GB_E((E_ + 255) / 256, T_);          // per-edge passes
    const int NB_AG = (MTOT * 8 + 255) / 256;       // 15625

    // CSR build (once, shared by both layers)
    init_k  <<<NB_M, 256>>>(deg, cnt);
    pass1_k <<<GB_E, 256>>>(deg, cnt, edge_index, edge_weight);
    scan1_k <<<NSCAN, 256>>>(cnt, offs, bsum);
    scan2_k <<<1, 32>>>(bsum, NSCAN);
    scan3_k <<<NB_M, 256>>>(offs, offw, bsum);
    dinv_all<<<NB_M, 256>>>(deg);
    scatter_k<<<GB_E, 256>>>(edge_index, edge_weight, deg, offw, bucket);

    // layer 1
    gemm_tc_k<128, 0><<<NB_G, 256, SM_TC1>>>(x, gcn1_w, nullptr, hw,
                                             nullptr, nullptr, nullptr);
    agg2_k<<<NB_AG, 256>>>(bucket, offs, offw, deg, hw, h1);

    // layer 2 (relu(h1+b1) fused into A-load)
    gemm_tc_k<64, 0><<<NB_G, 256, SM_TC2>>>(h1, gcn2_w, gcn1_b, hw,
                                            nullptr, nullptr, nullptr);
    agg2_k<<<NB_AG, 256>>>(bucket, offs, offw, deg, hw, h2);

    // K and V projections (fused relu(h2+b2), bias + permutation scatter)
    gemm_tc_k<64, 1><<<NB_G, 256, SM_TC2>>>(h2, in_proj_w + 64 * 64, gcn2_b, nullptr,
                                            in_proj_b + 64, global_idx, gk);
    gemm_tc_k<64, 1><<<NB_G, 256, SM_TC2>>>(h2, in_proj_w + 128 * 64, gcn2_b, nullptr,
                                            in_proj_b + 128, global_idx, gv);

    te9_k<<<(N_ * D_ + 255) / 256, 256>>>(h2, gcn2_b, global_idx, te9);

    tail_k<<<296, 128, TAIL_SMEM>>>(in_proj_w, in_proj_b, out_proj_w, out_proj_b,
                                    w1, w2, w3, w4, ln1_g, ln1_b, ln2_g, ln2_b,
                                    fc_w, fc_b, te9, gk, gv, out);
}

// round 6
// speedup vs baseline: 2.6208x; 1.0579x over previous
#include <cuda_runtime.h>
#include <cstdint>

#define T_   10
#define N_   50000
#define R_   50000
#define DIN_ 128
#define D_   64
#define H_   4
#define E_   400000
#define MTOT (T_ * N_)   // 500000
#define ETOT (T_ * E_)   // 4000000
#define SCAN_BLK 4096
#define NSCAN ((MTOT + SCAN_BLK - 1) / SCAN_BLK)   // 123

// ---------------- scratch ----------------
__device__ float g_deg[(size_t)MTOT];
__device__ int   g_cnt[(size_t)MTOT];
__device__ int   g_offs[(size_t)MTOT];
__device__ int   g_offw[(size_t)MTOT];
__device__ int   g_bsum[256];
__device__ int2  g_bucket[(size_t)ETOT];
__device__ float g_hw [(size_t)MTOT * D_];
__device__ float g_h1 [(size_t)MTOT * D_];
__device__ float g_h2 [(size_t)MTOT * D_];
__device__ float g_k  [(size_t)R_ * T_ * D_];
__device__ float g_v  [(size_t)R_ * T_ * D_];
__device__ float g_te9[(size_t)R_ * D_];

// ---------------- init / degree / count ----------------
__global__ void init_k(float* deg, int* cnt) {
    int i = blockIdx.x * blockDim.x + threadIdx.x;
    if (i < MTOT) { deg[i] = 1.0f; cnt[i] = 0; }
}
__global__ void pass1_k(float* deg, int* cnt, const int* __restrict__ edge_index,
                        const float* __restrict__ ew) {
    int t = blockIdx.y;
    int e = blockIdx.x * blockDim.x + threadIdx.x;
    if (e < E_) {
        int d = __ldg(edge_index + (size_t)t * 2 * E_ + E_ + e);
        atomicAdd(&deg[t * N_ + d], __ldg(ew + (size_t)t * E_ + e));
        atomicAdd(&cnt[t * N_ + d], 1);
    }
}

// ---------------- exclusive scan of cnt -> offs (+ dinv fused in scan3) ----------------
__global__ void scan1_k(const int* __restrict__ cnt, int* __restrict__ offs,
                        int* __restrict__ bsum) {
    __shared__ int ts[256];
    int b = blockIdx.x, tid = threadIdx.x;
    int base = b * SCAN_BLK + tid * 16;
    int v[16]; int s = 0;
#pragma unroll
    for (int i = 0; i < 16; i++) {
        int idx = base + i;
        v[i] = (idx < MTOT) ? cnt[idx] : 0;
        s += v[i];
    }
    ts[tid] = s;
    __syncthreads();
    for (int off = 1; off < 256; off <<= 1) {
        int x = (tid >= off) ? ts[tid - off] : 0;
        __syncthreads();
        ts[tid] += x;
        __syncthreads();
    }
    int excl = ts[tid] - s;
    if (tid == 255) bsum[b] = ts[255];
    int run = excl;
#pragma unroll
    for (int i = 0; i < 16; i++) {
        int idx = base + i;
        if (idx < MTOT) offs[idx] = run;
        run += v[i];
    }
}
__global__ void scan2_k(int* bsum, int nb) {
    if (threadIdx.x == 0) {
        int run = 0;
        for (int i = 0; i < nb; i++) { int v = bsum[i]; bsum[i] = run; run += v; }
    }
}
__global__ void scan3_k(int* __restrict__ offs, int* __restrict__ offw,
                        const int* __restrict__ bsum, float* __restrict__ deg) {
    int i = blockIdx.x * blockDim.x + threadIdx.x;
    if (i < MTOT) {
        int v = offs[i] + bsum[i >> 12];
        offs[i] = v;
        offw[i] = v;
        deg[i] = rsqrtf(deg[i]);   // fused dinv
    }
}

// ---------------- scatter edges into CSR buckets ----------------
__global__ void scatter_k(const int* __restrict__ edge_index, const float* __restrict__ ew,
                          const float* __restrict__ dinv, int* __restrict__ offw,
                          int2* __restrict__ bucket) {
    int t = blockIdx.y;
    int e = blockIdx.x * blockDim.x + threadIdx.x;
    if (e >= E_) return;
    const int* src = edge_index + (size_t)t * 2 * E_;
    int s = __ldg(src + e), d = __ldg(src + E_ + e);
    float w = __ldg(ew + (size_t)t * E_ + e);
    float c = __ldg(dinv + t * N_ + s) * w * __ldg(dinv + t * N_ + d);
    int pos = atomicAdd(&offw[t * N_ + d], 1);
    bucket[pos] = make_int2(s, __float_as_int(c));
}

// ---------------- gather aggregation ----------------
__global__ void agg2_k(const int2* __restrict__ bucket, const int* __restrict__ offs,
                       const int* __restrict__ offw, const float* __restrict__ dinv,
                       const float* __restrict__ hw, float* __restrict__ out) {
    int idx = blockIdx.x * blockDim.x + threadIdx.x;
    int node = idx >> 3, sub = idx & 7;
    if (node >= MTOT) return;
    long long tb = (long long)(node / N_) * N_;
    float di = __ldg(dinv + node);
    float s2 = di * di;
    const float4* hp = (const float4*)(hw + (size_t)node * 64) + 2 * sub;
    float4 a = __ldg(hp), b = __ldg(hp + 1);
    float4 acc0 = make_float4(a.x * s2, a.y * s2, a.z * s2, a.w * s2);
    float4 acc1 = make_float4(b.x * s2, b.y * s2, b.z * s2, b.w * s2);
    int p = __ldg(offs + node), e = __ldg(offw + node);
    for (; p < e; p++) {
        int2 ed = __ldg(bucket + p);
        float c = __int_as_float(ed.y);
        const float4* sp = (const float4*)(hw + (size_t)(tb + ed.x) * 64) + 2 * sub;
        float4 u = __ldg(sp), v = __ldg(sp + 1);
        acc0.x = fmaf(c, u.x, acc0.x); acc0.y = fmaf(c, u.y, acc0.y);
        acc0.z = fmaf(c, u.z, acc0.z); acc0.w = fmaf(c, u.w, acc0.w);
        acc1.x = fmaf(c, v.x, acc1.x); acc1.y = fmaf(c, v.y, acc1.y);
        acc1.z = fmaf(c, v.z, acc1.z); acc1.w = fmaf(c, v.w, acc1.w);
    }
    float4* op = (float4*)(out + (size_t)node * 64) + 2 * sub;
    op[0] = acc0;
    op[1] = acc1;
}

// ---------------- tf32 helpers ----------------
__device__ __forceinline__ void mma_tf32(float* c, unsigned a0, unsigned a1,
                                         unsigned a2, unsigned a3,
                                         unsigned b0, unsigned b1) {
    asm volatile(
        "mma.sync.aligned.m16n8k8.row.col.f32.tf32.tf32.f32 "
        "{%0,%1,%2,%3}, {%4,%5,%6,%7}, {%8,%9}, {%0,%1,%2,%3};"
        : "+f"(c[0]), "+f"(c[1]), "+f"(c[2]), "+f"(c[3])
        : "r"(a0), "r"(a1), "r"(a2), "r"(a3), "r"(b0), "r"(b1));
}
__device__ __forceinline__ void split_tf32(float f, unsigned& hi, unsigned& lo) {
    unsigned u = __float_as_uint(f) & 0xFFFFE000u;
    hi = u;
    lo = __float_as_uint(f - __uint_as_float(u));
}

// ---------------- GEMM: C[M x 64] = act(A[M x K]) @ W[64 x K]^T -> hw ----------------
template <int K>
__global__ void __launch_bounds__(256, 2)
gemm_tc_k(const float* __restrict__ A, const float* __restrict__ Wsrc,
          const float* __restrict__ abias, float* __restrict__ hw) {
    constexpr int BM = 128, BK = 32;
    constexpr int NT = K / BK;
    constexpr int WPAD = K + 4;
    constexpr int APAD = BK + 4;

    extern __shared__ float sm[];
    float* Wsh = sm;
    float* Ash = sm + 64 * WPAD;

    const int tid = threadIdx.x;
    const int wid = tid >> 5, lane = tid & 31;
    const int warp_m = wid & 3, warp_n = wid >> 2;
    const int lg = lane >> 2, lt = lane & 3;
    const long long row0 = (long long)blockIdx.x * BM;

    for (int i = tid * 4; i < 64 * K; i += 256 * 4) {
        int n = i / K, k = i % K;
        float4 w = *(const float4*)(Wsrc + n * K + k);
        *(float4*)(Wsh + n * WPAD + k) = w;
    }

    float4 areg[4];
    auto lda = [&](int kt) {
#pragma unroll
        for (int it = 0; it < 4; it++) {
            int idx = it * 256 + tid;
            int r = idx >> 3, kq = idx & 7;
            long long grow = row0 + r;
            float4 v = make_float4(0.f, 0.f, 0.f, 0.f);
            if (grow < MTOT) {
                v = *(const float4*)(A + grow * K + kt * BK + kq * 4);
                if (abias) {
                    float4 b = *(const float4*)(abias + kt * BK + kq * 4);
                    v.x = fmaxf(v.x + b.x, 0.f);
                    v.y = fmaxf(v.y + b.y, 0.f);
                    v.z = fmaxf(v.z + b.z, 0.f);
                    v.w = fmaxf(v.w + b.w, 0.f);
                }
            }
            areg[it] = v;
        }
    };
    auto sts = [&](int buf) {
        float* dst = Ash + buf * BM * APAD;
#pragma unroll
        for (int it = 0; it < 4; it++) {
            int idx = it * 256 + tid;
            int r = idx >> 3, kq = idx & 7;
            *(float4*)(dst + r * APAD + kq * 4) = areg[it];
        }
    };

    float c[2][4][4];
#pragma unroll
    for (int mt = 0; mt < 2; mt++)
#pragma unroll
        for (int nt = 0; nt < 4; nt++)
#pragma unroll
            for (int i = 0; i < 4; i++) c[mt][nt][i] = 0.f;

    lda(0);
    sts(0);

    for (int kt = 0; kt < NT; kt++) {
        __syncthreads();
        if (kt + 1 < NT) lda(kt + 1);
        const float* As = Ash + (kt & 1) * BM * APAD;
#pragma unroll
        for (int ks = 0; ks < 4; ks++) {
            const int k0 = ks * 8 + lt;
            unsigned ahi[2][4], alo[2][4];
#pragma unroll
            for (int mt = 0; mt < 2; mt++) {
                int ar = warp_m * 32 + mt * 16 + lg;
                float f0 = As[ar * APAD + k0];
                float f1 = As[(ar + 8) * APAD + k0];
                float f2 = As[ar * APAD + k0 + 4];
                float f3 = As[(ar + 8) * APAD + k0 + 4];
                split_tf32(f0, ahi[mt][0], alo[mt][0]);
                split_tf32(f1, ahi[mt][1], alo[mt][1]);
                split_tf32(f2, ahi[mt][2], alo[mt][2]);
                split_tf32(f3, ahi[mt][3], alo[mt][3]);
            }
            unsigned bhi[4][2], blo[4][2];
#pragma unroll
            for (int nt = 0; nt < 4; nt++) {
                int bn = warp_n * 32 + nt * 8 + lg;
                float g0 = Wsh[bn * WPAD + kt * BK + k0];
                float g1 = Wsh[bn * WPAD + kt * BK + k0 + 4];
                split_tf32(g0, bhi[nt][0], blo[nt][0]);
                split_tf32(g1, bhi[nt][1], blo[nt][1]);
            }
#pragma unroll
            for (int mt = 0; mt < 2; mt++)
#pragma unroll
                for (int nt = 0; nt < 4; nt++) {
                    mma_tf32(c[mt][nt], ahi[mt][0], ahi[mt][1], ahi[mt][2], ahi[mt][3],
                             bhi[nt][0], bhi[nt][1]);
                    mma_tf32(c[mt][nt], alo[mt][0], alo[mt][1], alo[mt][2], alo[mt][3],
                             bhi[nt][0], bhi[nt][1]);
                    mma_tf32(c[mt][nt], ahi[mt][0], ahi[mt][1], ahi[mt][2], ahi[mt][3],
                             blo[nt][0], blo[nt][1]);
                }
        }
        if (kt + 1 < NT) sts((kt + 1) & 1);
    }

#pragma unroll
    for (int mt = 0; mt < 2; mt++) {
        long long r_lo = row0 + warp_m * 32 + mt * 16 + lg;
#pragma unroll
        for (int half = 0; half < 2; half++) {
            long long r = r_lo + half * 8;
            if (r >= MTOT) continue;
#pragma unroll
            for (int nt = 0; nt < 4; nt++) {
                int col = warp_n * 32 + nt * 8 + 2 * lt;
                *(float2*)(hw + r * 64 + col) =
                    make_float2(c[mt][nt][half * 2 + 0], c[mt][nt][half * 2 + 1]);
            }
        }
    }
}

// ---------------- merged K+V projection GEMM: C[M x 128], scatter split ----------------
// A = relu(h2 + b2), W = in_proj_w rows 64..191 (128 x 64), bias ebias = in_proj_b + 64.
__global__ void __launch_bounds__(512, 1)
gemm_kv_k(const float* __restrict__ A, const float* __restrict__ Wsrc,
          const float* __restrict__ abias, const float* __restrict__ ebias,
          const int* __restrict__ gidx, float* __restrict__ gK, float* __restrict__ gV) {
    constexpr int K = 64, BM = 128, BK = 32, NT = 2;
    constexpr int WPAD = K + 4;   // 68
    constexpr int APAD = BK + 4;  // 36

    extern __shared__ float sm[];
    float* Wsh = sm;                    // 128 * 68
    float* Ash = sm + 128 * WPAD;       // 2 * 128 * 36

    const int tid = threadIdx.x;
    const int wid = tid >> 5, lane = tid & 31;
    const int warp_m = wid & 3, warp_n = wid >> 2;   // 4 x 4 warps
    const int lg = lane >> 2, lt = lane & 3;
    const long long row0 = (long long)blockIdx.x * BM;

    for (int i = tid * 4; i < 128 * K; i += 512 * 4) {
        int n = i / K, k = i % K;
        float4 w = *(const float4*)(Wsrc + n * K + k);
        *(float4*)(Wsh + n * WPAD + k) = w;
    }

    float4 areg[2];
    auto lda = [&](int kt) {
#pragma unroll
        for (int it = 0; it < 2; it++) {
            int idx = it * 512 + tid;
            int r = idx >> 3, kq = idx & 7;
            long long grow = row0 + r;
            float4 v = make_float4(0.f, 0.f, 0.f, 0.f);
            if (grow < MTOT) {
                v = *(const float4*)(A + grow * K + kt * BK + kq * 4);
                float4 b = *(const float4*)(abias + kt * BK + kq * 4);
                v.x = fmaxf(v.x + b.x, 0.f);
                v.y = fmaxf(v.y + b.y, 0.f);
                v.z = fmaxf(v.z + b.z, 0.f);
                v.w = fmaxf(v.w + b.w, 0.f);
            }
            areg[it] = v;
        }
    };
    auto sts = [&](int buf) {
        float* dst = Ash + buf * BM * APAD;
#pragma unroll
        for (int it = 0; it < 2; it++) {
            int idx = it * 512 + tid;
            int r = idx >> 3, kq = idx & 7;
            *(float4*)(dst + r * APAD + kq * 4) = areg[it];
        }
    };

    float c[2][4][4];
#pragma unroll
    for (int mt = 0; mt < 2; mt++)
#pragma unroll
        for (int nt = 0; nt < 4; nt++)
#pragma unroll
            for (int i = 0; i < 4; i++) c[mt][nt][i] = 0.f;

    lda(0);
    sts(0);

    for (int kt = 0; kt < NT; kt++) {
        __syncthreads();
        if (kt + 1 < NT) lda(kt + 1);
        const float* As = Ash + (kt & 1) * BM * APAD;
#pragma unroll
        for (int ks = 0; ks < 4; ks++) {
            const int k0 = ks * 8 + lt;
            unsigned ahi[2][4], alo[2][4];
#pragma unroll
            for (int mt = 0; mt < 2; mt++) {
                int ar = warp_m * 32 + mt * 16 + lg;
                float f0 = As[ar * APAD + k0];
                float f1 = As[(ar + 8) * APAD + k0];
                float f2 = As[ar * APAD + k0 + 4];
                float f3 = As[(ar + 8) * APAD + k0 + 4];
                split_tf32(f0, ahi[mt][0], alo[mt][0]);
                split_tf32(f1, ahi[mt][1], alo[mt][1]);
                split_tf32(f2, ahi[mt][2], alo[mt][2]);
                split_tf32(f3, ahi[mt][3], alo[mt][3]);
            }
            unsigned bhi[4][2], blo[4][2];
#pragma unroll
            for (int nt = 0; nt < 4; nt++) {
                int bn = warp_n * 32 + nt * 8 + lg;   // 0..127
                float g0 = Wsh[bn * WPAD + kt * BK + k0];
                float g1 = Wsh[bn * WPAD + kt * BK + k0 + 4];
                split_tf32(g0, bhi[nt][0], blo[nt][0]);
                split_tf32(g1, bhi[nt][1], blo[nt][1]);
            }
#pragma unroll
            for (int mt = 0; mt < 2; mt++)
#pragma unroll
                for (int nt = 0; nt < 4; nt++) {
                    mma_tf32(c[mt][nt], ahi[mt][0], ahi[mt][1], ahi[mt][2], ahi[mt][3],
                             bhi[nt][0], bhi[nt][1]);
                    mma_tf32(c[mt][nt], alo[mt][0], alo[mt][1], alo[mt][2], alo[mt][3],
                             bhi[nt][0], bhi[nt][1]);
                    mma_tf32(c[mt][nt], ahi[mt][0], ahi[mt][1], ahi[mt][2], ahi[mt][3],
                             blo[nt][0], blo[nt][1]);
                }
        }
        if (kt + 1 < NT) sts((kt + 1) & 1);
    }

#pragma unroll
    for (int mt = 0; mt < 2; mt++) {
        long long r_lo = row0 + warp_m * 32 + mt * 16 + lg;
#pragma unroll
        for (int half = 0; half < 2; half++) {
            long long r = r_lo + half * 8;
            if (r >= MTOT) continue;
            unsigned rr = (unsigned)r;
            unsigned t = rr / (unsigned)N_;
            unsigned n = rr - t * (unsigned)N_;
            int ridx = __ldg(gidx + (size_t)t * R_ + n);
            size_t rowoff = ((size_t)ridx * T_ + t) * 64;
#pragma unroll
            for (int nt = 0; nt < 4; nt++) {
                int col = warp_n * 32 + nt * 8 + 2 * lt;   // 0..127
                float2 b = *(const float2*)(ebias + col);
                float* base = (col < 64 ? gK + rowoff + col : gV + rowoff + (col - 64));
                *(float2*)base = make_float2(c[mt][nt][half * 2 + 0] + b.x,
                                             c[mt][nt][half * 2 + 1] + b.y);
            }
        }
    }
}

// ---------------- te9: relu(h2[t=9] + b2) scattered by gidx ----------------
__global__ void te9_k(const float* __restrict__ h2, const float* __restrict__ b2,
                      const int* __restrict__ gidx, float* __restrict__ te9) {
    int idx = blockIdx.x * blockDim.x + threadIdx.x;
    if (idx >= N_ * D_) return;
    int n = idx >> 6, c = idx & 63;
    float v = fmaxf(h2[((size_t)9 * N_ + n) * 64 + c] + b2[c], 0.f);
    te9[(size_t)__ldg(gidx + (size_t)9 * R_ + n) * 64 + c] = v;
}

// ---------------- tail ----------------
#define TAIL_WARPS 8
#define TAIL_SMEM  ((12288 + 704 + TAIL_WARPS * 1456) * 4)

__device__ __forceinline__ float warp_sum(float v) {
#pragma unroll
    for (int off = 16; off; off >>= 1) v += __shfl_xor_sync(0xffffffffu, v, off);
    return v;
}

__global__ void tail_k(const float* __restrict__ inW, const float* __restrict__ inB,
                       const float* __restrict__ outW, const float* __restrict__ outB,
                       const float* __restrict__ w1, const float* __restrict__ w2,
                       const float* __restrict__ w3, const float* __restrict__ w4,
                       const float* __restrict__ ln1g, const float* __restrict__ ln1b,
                       const float* __restrict__ ln2g, const float* __restrict__ ln2b,
                       const float* __restrict__ fcW, const float* __restrict__ fcB,
                       const float* __restrict__ te9, const float* __restrict__ gK,
                       const float* __restrict__ gV, float* __restrict__ out) {
    extern __shared__ float sh[];
    float* Wq = sh;
    float* Wo = sh + 4096;
    float* Wf = sh + 8192;
    float* cv = sh + 12288;

    int tid = threadIdx.x;
    for (int i = tid; i < 4096; i += TAIL_WARPS * 32) {
        int k = i >> 6, j = i & 63;
        Wq[i] = inW[j * 64 + k];
        Wo[i] = outW[j * 64 + k];
        Wf[i] = fcW[j * 64 + k];
    }
    if (tid < 64) {
        cv[tid]       = inB[tid];
        cv[64 + tid]  = outB[tid];
        cv[128 + tid] = fcB[tid];
        cv[192 + tid] = w1[(T_ - 1) * 64 + tid];
        cv[256 + tid] = w2[(T_ - 1) * 64 + tid];
        cv[320 + tid] = ln1g[tid];
        cv[384 + tid] = ln1b[tid];
        cv[448 + tid] = w3[tid];
        cv[512 + tid] = w4[tid];
        cv[576 + tid] = ln2g[tid];
        cv[640 + tid] = ln2b[tid];
    }
    __syncthreads();

    int warp = tid >> 5, lane = tid & 31;
    float* wb   = cv + 704 + warp * 1456;
    float* pvec = wb;
    float* pq   = wb + 64;
    float* kb   = wb + 128;
    float* vb   = wb + 768;
    float* sc   = wb + 1408;

    int gw = blockIdx.x * TAIL_WARPS + warp;
    int nw = gridDim.x * TAIL_WARPS;

    for (int r = gw; r < R_; r += nw) {
        pvec[lane]      = te9[(size_t)r * 64 + lane];
        pvec[lane + 32] = te9[(size_t)r * 64 + lane + 32];
        for (int i = lane; i < 640; i += 32) {
            kb[i] = gK[(size_t)r * 640 + i];
            vb[i] = gV[(size_t)r * 640 + i];
        }
        __syncwarp();

        float q0 = cv[lane], q1 = cv[lane + 32];
        for (int k = 0; k < 64; k++) {
            float xv = pvec[k];
            q0 = fmaf(xv, Wq[k * 64 + lane], q0);
            q1 = fmaf(xv, Wq[k * 64 + lane + 32], q1);
        }
        pq[lane] = q0; pq[lane + 32] = q1;
        __syncwarp();

        for (int p = lane; p < H_ * T_; p += 32) {
            int h = p / T_, tt = p - h * T_;
            const float* qh = pq + h * 16;
            const float* kh = kb + tt * 64 + h * 16;
            float s = 0.f;
#pragma unroll
            for (int d = 0; d < 16; d++) s = fmaf(qh[d], kh[d], s);
            sc[p] = s * 0.25f;
        }
        __syncwarp();

        if (lane < H_) {
            float mx = -1e30f;
#pragma unroll
            for (int tt = 0; tt < T_; tt++) mx = fmaxf(mx, sc[lane * T_ + tt]);
            float sm = 0.f;
#pragma unroll
            for (int tt = 0; tt < T_; tt++) {
                float ev = __expf(sc[lane * T_ + tt] - mx);
                sc[lane * T_ + tt] = ev; sm += ev;
            }
            float inv = 1.f / sm;
#pragma unroll
            for (int tt = 0; tt < T_; tt++) sc[lane * T_ + tt] *= inv;
        }
        __syncwarp();

        int h0 = lane >> 4, h1 = (lane + 32) >> 4;
        float a0 = 0.f, a1 = 0.f;
#pragma unroll
        for (int tt = 0; tt < T_; tt++) {
            a0 = fmaf(sc[h0 * T_ + tt], vb[tt * 64 + lane], a0);
            a1 = fmaf(sc[h1 * T_ + tt], vb[tt * 64 + lane + 32], a1);
        }
        pq[lane] = a0; pq[lane + 32] = a1;
        __syncwarp();

        float o0 = cv[64 + lane], o1 = cv[64 + lane + 32];
        for (int k = 0; k < 64; k++) {
            float xv = pq[k];
            o0 = fmaf(xv, Wo[k * 64 + lane], o0);
            o1 = fmaf(xv, Wo[k * 64 + lane + 32], o1);
        }

        float y0 = cv[192 + lane] * pvec[lane] + cv[256 + lane] * o0;
        float y1 = cv[192 + lane + 32] * pvec[lane + 32] + cv[256 + lane + 32] * o1;
        float mu = warp_sum(y0 + y1) * (1.f / 64.f);
        float d0 = y0 - mu, d1 = y1 - mu;
        float var = warp_sum(d0 * d0 + d1 * d1) * (1.f / 64.f);
        float rs = rsqrtf(var + 1e-5f);
        float f0 = d0 * rs * cv[320 + lane] + cv[384 + lane];
        float f1 = d1 * rs * cv[320 + lane + 32] + cv[384 + lane + 32];
        __syncwarp();
        pvec[lane] = f0; pvec[lane + 32] = f1;
        __syncwarp();

        float u0 = cv[128 + lane], u1 = cv[128 + lane + 32];
        for (int k = 0; k < 64; k++) {
            float xv = pvec[k];
            u0 = fmaf(xv, Wf[k * 64 + lane], u0);
            u1 = fmaf(xv, Wf[k * 64 + lane + 32], u1);
        }
        float z0 = cv[448 + lane] * f0 + cv[512 + lane] * u0;
        float z1 = cv[448 + lane + 32] * f1 + cv[512 + lane + 32] * u1;
        float mu2 = warp_sum(z0 + z1) * (1.f / 64.f);
        float e0 = z0 - mu2, e1 = z1 - mu2;
        float var2 = warp_sum(e0 * e0 + e1 * e1) * (1.f / 64.f);
        float rs2 = rsqrtf(var2 + 1e-5f);
        out[(size_t)r * 64 + lane]      = e0 * rs2 * cv[576 + lane] + cv[640 + lane];
        out[(size_t)r * 64 + lane + 32] = e1 * rs2 * cv[576 + lane + 32] + cv[640 + lane + 32];
        __syncwarp();
    }
}

// ---------------- launch ----------------
extern "C" void kernel_launch(void* const* d_in, const int* in_sizes, int n_in,
                              void* d_out, int out_size) {
    const float* x          = (const float*)d_in[0];
    const int*   edge_index = (const int*)  d_in[1];
    const float* edge_weight= (const float*)d_in[2];
    const int*   global_idx = (const int*)  d_in[3];
    const float* gcn1_w     = (const float*)d_in[4];
    const float* gcn1_b     = (const float*)d_in[5];
    const float* gcn2_w     = (const float*)d_in[6];
    const float* gcn2_b     = (const float*)d_in[7];
    const float* in_proj_w  = (const float*)d_in[8];
    const float* in_proj_b  = (const float*)d_in[9];
    const float* out_proj_w = (const float*)d_in[10];
    const float* out_proj_b = (const float*)d_in[11];
    const float* w1         = (const float*)d_in[12];
    const float* w2         = (const float*)d_in[13];
    const float* w3         = (const float*)d_in[14];
    const float* w4         = (const float*)d_in[15];
    const float* ln1_g      = (const float*)d_in[16];
    const float* ln1_b      = (const float*)d_in[17];
    const float* ln2_g      = (const float*)d_in[18];
    const float* ln2_b      = (const float*)d_in[19];
    const float* fc_w       = (const float*)d_in[20];
    const float* fc_b       = (const float*)d_in[21];
    float* out = (float*)d_out;

    float *deg, *hw, *h1, *h2, *gk, *gv, *te9;
    int *cnt, *offs, *offw, *bsum;
    int2* bucket;
    cudaGetSymbolAddress((void**)&deg,  g_deg);
    cudaGetSymbolAddress((void**)&cnt,  g_cnt);
    cudaGetSymbolAddress((void**)&offs, g_offs);
    cudaGetSymbolAddress((void**)&offw, g_offw);
    cudaGetSymbolAddress((void**)&bsum, g_bsum);
    cudaGetSymbolAddress((void**)&bucket, g_bucket);
    cudaGetSymbolAddress((void**)&hw,  g_hw);
    cudaGetSymbolAddress((void**)&h1,  g_h1);
    cudaGetSymbolAddress((void**)&h2,  g_h2);
    cudaGetSymbolAddress((void**)&gk,  g_k);
    cudaGetSymbolAddress((void**)&gv,  g_v);
    cudaGetSymbolAddress((void**)&te9, g_te9);

    const int SM_TC1 = (64 * (128 + 4) + 2 * 128 * 36) * 4;  // 70656
    const int SM_TC2 = (64 * (64 + 4)  + 2 * 128 * 36) * 4;  // 54272
    const int SM_KV  = (128 * (64 + 4) + 2 * 128 * 36) * 4;  // 71680
    cudaFuncSetAttribute((const void*)gemm_tc_k<128>,
                         cudaFuncAttributeMaxDynamicSharedMemorySize, SM_TC1);
    cudaFuncSetAttribute((const void*)gemm_tc_k<64>,
                         cudaFuncAttributeMaxDynamicSharedMemorySize, SM_TC2);
    cudaFuncSetAttribute((const void*)gemm_kv_k,
                         cudaFuncAttributeMaxDynamicSharedMemorySize, SM_KV);
    cudaFuncSetAttribute(tail_k, cudaFuncAttributeMaxDynamicSharedMemorySize, TAIL_SMEM);

    const int NB_M  = (MTOT + 255) / 256;
    const int NB_G  = (MTOT + 127) / 128;           // 3907
    const dim3 GB_E((E_ + 255) / 256, T_);
    const int NB_AG = (MTOT * 8 + 255) / 256;       // 15625

    // CSR build (once, shared by both layers)
    init_k  <<<NB_M, 256>>>(deg, cnt);
    pass1_k <<<GB_E, 256>>>(deg, cnt, edge_index, edge_weight);
    scan1_k <<<NSCAN, 256>>>(cnt, offs, bsum);
    scan2_k <<<1, 32>>>(bsum, NSCAN);
    scan3_k <<<NB_M, 256>>>(offs, offw, bsum, deg);   // also dinv
    scatter_k<<<GB_E, 256>>>(edge_index, edge_weight, deg, offw, bucket);

    // layer 1
    gemm_tc_k<128><<<NB_G, 256, SM_TC1>>>(x, gcn1_w, nullptr, hw);
    agg2_k<<<NB_AG, 256>>>(bucket, offs, offw, deg, hw, h1);

    // layer 2 (relu(h1+b1) fused into A-load)
    gemm_tc_k<64><<<NB_G, 256, SM_TC2>>>(h1, gcn2_w, gcn1_b, hw);
    agg2_k<<<NB_AG, 256>>>(bucket, offs, offw, deg, hw, h2);

    // merged K+V projection (relu(h2+b2) fused, bias + permutation scatter)
    gemm_kv_k<<<NB_G, 512, SM_KV>>>(h2, in_proj_w + 64 * 64, gcn2_b,
                                    in_proj_b + 64, global_idx, gk, gv);

    te9_k<<<(N_ * D_ + 255) / 256, 256>>>(h2, gcn2_b, global_idx, te9);

    tail_k<<<296, TAIL_WARPS * 32, TAIL_SMEM>>>(in_proj_w, in_proj_b, out_proj_w, out_proj_b,
                                                w1, w2, w3, w4, ln1_g, ln1_b, ln2_g, ln2_b,
                                                fc_w, fc_b, te9, gk, gv, out);
}